// round 1
// baseline (speedup 1.0000x reference)
#include <cuda_runtime.h>
#include <math.h>

// ---------------- problem constants ----------------
#define DIM   256
#define HEADS 8
#define HD    32
#define PL    8
#define LAT   60
#define LON   120
#define WPL   2
#define WLAT  6
#define WLON  12
#define NTOK  144            // tokens per window
#define NPL   (PL/WPL)       // 4
#define NLAT  (LAT/WLAT)     // 10
#define NLON  (LON/WLON)     // 10
#define NW    (NPL*NLAT)     // 40 window types
#define BATCH 2
#define LTOK  (PL*LAT*LON)   // 57600
#define MTOK  (BATCH*LTOK)   // 115200
#define HID   1024
#define QKS   33             // padded stride for q/k/v in smem

// ---------------- scratch (static device globals; no allocation) ----------------
__device__ float g_hw  [(size_t)MTOK*DIM];     // LN1 output, window-ordered
__device__ float g_qkv [(size_t)MTOK*3*DIM];   // window-ordered qkv
__device__ float g_attn[(size_t)MTOK*DIM];     // window-ordered attention output
__device__ float g_proj[(size_t)MTOK*DIM];     // window-ordered proj output
__device__ float g_x2  [(size_t)MTOK*DIM];     // token-ordered residual (x + attn branch)
__device__ float g_ln2 [(size_t)MTOK*DIM];     // token-ordered LN2 output
__device__ float g_fc1 [(size_t)MTOK*HID];     // token-ordered fc1+gelu output

// ---------------- helpers ----------------
__device__ __forceinline__ int win_index(int t) {
    // token-order index -> window-order index (window_partition permutation)
    int b   = t / LTOK;
    int rem = t - b * LTOK;
    int pl  = rem / (LAT * LON);
    int r2  = rem - pl * (LAT * LON);
    int lat = r2 / LON;
    int lon = r2 - lat * LON;
    int np = pl / WPL,  ip = pl - np * WPL;
    int nl = lat / WLAT, il = lat - nl * WLAT;
    int no = lon / WLON, io = lon - no * WLON;
    int wb = b * NLON + no;          // window batch  (B * nLon)
    int w  = np * NLAT + nl;         // window type   (nPl * nLat)
    int n  = (ip * WLAT + il) * WLON + io;
    return (wb * NW + w) * NTOK + n;
}

__device__ __forceinline__ void blk_reduce2(float& a, float& b) {
    #pragma unroll
    for (int o = 16; o > 0; o >>= 1) {
        a += __shfl_xor_sync(0xffffffffu, a, o);
        b += __shfl_xor_sync(0xffffffffu, b, o);
    }
    __shared__ float sa[8], sb[8];
    int w = threadIdx.x >> 5, l = threadIdx.x & 31;
    if (l == 0) { sa[w] = a; sb[w] = b; }
    __syncthreads();
    float ta = 0.f, tb = 0.f;
    #pragma unroll
    for (int i = 0; i < 8; i++) { ta += sa[i]; tb += sb[i]; }
    a = ta; b = tb;
}

// ---------------- LN1 (+ window partition scatter) ----------------
__global__ void ln1_kernel(const float* __restrict__ x,
                           const float* __restrict__ g,
                           const float* __restrict__ b) {
    int t = blockIdx.x, c = threadIdx.x;
    float v = x[(size_t)t * DIM + c];
    float s = v, q = v * v;
    blk_reduce2(s, q);
    float mu  = s * (1.0f / DIM);
    float var = q * (1.0f / DIM) - mu * mu;
    float y = (v - mu) * rsqrtf(fmaxf(var, 0.f) + 1e-5f) * g[c] + b[c];
    g_hw[(size_t)win_index(t) * DIM + c] = y;
}

// ---------------- residual add (window reverse gather) + LN2 ----------------
__global__ void add_ln2_kernel(const float* __restrict__ x,
                               const float* __restrict__ g,
                               const float* __restrict__ b) {
    int t = blockIdx.x, c = threadIdx.x;
    float v = x[(size_t)t * DIM + c] + g_proj[(size_t)win_index(t) * DIM + c];
    g_x2[(size_t)t * DIM + c] = v;
    float s = v, q = v * v;
    blk_reduce2(s, q);
    float mu  = s * (1.0f / DIM);
    float var = q * (1.0f / DIM) - mu * mu;
    g_ln2[(size_t)t * DIM + c] =
        (v - mu) * rsqrtf(fmaxf(var, 0.f) + 1e-5f) * g[c] + b[c];
}

// ---------------- SGEMM: C[M,N] = A[M,K] @ W[N,K]^T + bias (+gelu) (+residual) ----------------
// BM=BN=128, BK=8, 256 threads, 8x8 per thread. M%128==0, N%128==0, K%8==0.
template<bool GELU, bool RES>
__global__ void sgemm_kernel(const float* __restrict__ A,
                             const float* __restrict__ W,
                             const float* __restrict__ bias,
                             const float* __restrict__ res,
                             float* __restrict__ C,
                             int M, int N, int K) {
    __shared__ float As[8][128];
    __shared__ float Bs[8][128];
    int tid = threadIdx.x;
    int bm = blockIdx.y * 128;
    int bn = blockIdx.x * 128;
    int tx = tid & 15, ty = tid >> 4;
    int lrow  = tid >> 1;
    int lcol4 = (tid & 1) * 4;

    float acc[8][8];
    #pragma unroll
    for (int i = 0; i < 8; i++)
        #pragma unroll
        for (int j = 0; j < 8; j++) acc[i][j] = 0.f;

    for (int k0 = 0; k0 < K; k0 += 8) {
        float4 a4 = *(const float4*)&A[(size_t)(bm + lrow) * K + k0 + lcol4];
        float4 b4 = *(const float4*)&W[(size_t)(bn + lrow) * K + k0 + lcol4];
        As[lcol4 + 0][lrow] = a4.x; As[lcol4 + 1][lrow] = a4.y;
        As[lcol4 + 2][lrow] = a4.z; As[lcol4 + 3][lrow] = a4.w;
        Bs[lcol4 + 0][lrow] = b4.x; Bs[lcol4 + 1][lrow] = b4.y;
        Bs[lcol4 + 2][lrow] = b4.z; Bs[lcol4 + 3][lrow] = b4.w;
        __syncthreads();
        #pragma unroll
        for (int kk = 0; kk < 8; kk++) {
            float4 a0 = *(const float4*)&As[kk][ty * 8];
            float4 a1 = *(const float4*)&As[kk][ty * 8 + 4];
            float4 b0 = *(const float4*)&Bs[kk][tx * 8];
            float4 b1 = *(const float4*)&Bs[kk][tx * 8 + 4];
            float ra[8] = {a0.x, a0.y, a0.z, a0.w, a1.x, a1.y, a1.z, a1.w};
            float rb[8] = {b0.x, b0.y, b0.z, b0.w, b1.x, b1.y, b1.z, b1.w};
            #pragma unroll
            for (int i = 0; i < 8; i++)
                #pragma unroll
                for (int j = 0; j < 8; j++)
                    acc[i][j] += ra[i] * rb[j];
        }
        __syncthreads();
    }

    #pragma unroll
    for (int i = 0; i < 8; i++) {
        size_t m = bm + ty * 8 + i;
        size_t rowoff = m * (size_t)N + bn + tx * 8;
        #pragma unroll
        for (int j = 0; j < 8; j++) {
            float v = acc[i][j] + bias[bn + tx * 8 + j];
            if (GELU) v = 0.5f * v * (1.0f + erff(v * 0.70710678118654752f));
            if (RES)  v += res[rowoff + j];
            C[rowoff + j] = v;
        }
    }
}

// ---------------- windowed attention with earth position bias ----------------
// grid: (800 windows, 8 heads); block: 256 threads; dyn smem: q/k/v (stride 33) + 144x144 scores
__global__ void attn_kernel(const float* __restrict__ bias_table) {
    extern __shared__ float sm[];
    float* sq = sm;
    float* sk = sq + NTOK * QKS;
    float* sv = sk + NTOK * QKS;
    float* sp = sv + NTOK * QKS;   // [144][144]

    int wg = blockIdx.x;           // global window 0..799
    int h  = blockIdx.y;           // head
    int wt = wg % NW;              // window type for bias
    int tid = threadIdx.x;
    size_t base = (size_t)wg * NTOK;
    const float scale = 0.17677669529663687f;  // 32^-0.5

    // load q (scaled), k, v
    for (int idx = tid; idx < NTOK * HD; idx += 256) {
        int n = idx >> 5, e = idx & 31;
        size_t toff = (base + n) * (size_t)(3 * DIM);
        sq[n * QKS + e] = g_qkv[toff +            h * HD + e] * scale;
        sk[n * QKS + e] = g_qkv[toff + DIM     +  h * HD + e];
        sv[n * QKS + e] = g_qkv[toff + 2 * DIM +  h * HD + e];
    }
    __syncthreads();

    // scores: thread (ty,tx) owns i = ty+16a, j = tx+16b (9x9 tile)
    int ty = tid >> 4, tx = tid & 15;
    float acc[9][9];
    #pragma unroll
    for (int a = 0; a < 9; a++)
        #pragma unroll
        for (int b = 0; b < 9; b++) acc[a][b] = 0.f;

    #pragma unroll 4
    for (int e = 0; e < HD; e++) {
        float rq[9], rk[9];
        #pragma unroll
        for (int a = 0; a < 9; a++) rq[a] = sq[(ty + 16 * a) * QKS + e];
        #pragma unroll
        for (int b = 0; b < 9; b++) rk[b] = sk[(tx + 16 * b) * QKS + e];
        #pragma unroll
        for (int a = 0; a < 9; a++)
            #pragma unroll
            for (int b = 0; b < 9; b++)
                acc[a][b] += rq[a] * rk[b];
    }

    // add earth position bias, write scores
    #pragma unroll
    for (int a = 0; a < 9; a++) {
        int i = ty + 16 * a;
        int ipl = i / 72, ilat = (i / 12) % 6, ilon = i % 12;
        #pragma unroll
        for (int b = 0; b < 9; b++) {
            int j = tx + 16 * b;
            int jpl = j / 72, jlat = (j / 12) % 6, jlon = j % 12;
            int bidx = (ipl + jpl * 2) * 828 + (ilat + jlat * 6) * 23 + (ilon - jlon + 11);
            float bv = bias_table[((size_t)bidx * NW + wt) * HEADS + h];
            sp[i * NTOK + j] = acc[a][b] + bv;
        }
    }
    __syncthreads();

    // softmax: warp per row
    int warp = tid >> 5, lane = tid & 31;
    for (int r = warp; r < NTOK; r += 8) {
        float mx = -1e30f;
        for (int j = lane; j < NTOK; j += 32) mx = fmaxf(mx, sp[r * NTOK + j]);
        #pragma unroll
        for (int o = 16; o > 0; o >>= 1) mx = fmaxf(mx, __shfl_xor_sync(0xffffffffu, mx, o));
        float sum = 0.f;
        for (int j = lane; j < NTOK; j += 32) {
            float p = __expf(sp[r * NTOK + j] - mx);
            sp[r * NTOK + j] = p;
            sum += p;
        }
        #pragma unroll
        for (int o = 16; o > 0; o >>= 1) sum += __shfl_xor_sync(0xffffffffu, sum, o);
        float inv = 1.0f / sum;
        for (int j = lane; j < NTOK; j += 32) sp[r * NTOK + j] *= inv;
    }
    __syncthreads();

    // PV: thread owns i = ty+16a (9 rows), e = tx*2 + {0,1}
    float o0[9], o1[9];
    #pragma unroll
    for (int a = 0; a < 9; a++) { o0[a] = 0.f; o1[a] = 0.f; }
    for (int j = 0; j < NTOK; j++) {
        float v0 = sv[j * QKS + tx * 2];
        float v1 = sv[j * QKS + tx * 2 + 1];
        #pragma unroll
        for (int a = 0; a < 9; a++) {
            float p = sp[(ty + 16 * a) * NTOK + j];
            o0[a] += p * v0;
            o1[a] += p * v1;
        }
    }
    #pragma unroll
    for (int a = 0; a < 9; a++) {
        int n = ty + 16 * a;
        size_t off = (base + n) * (size_t)DIM + h * HD + tx * 2;
        g_attn[off]     = o0[a];
        g_attn[off + 1] = o1[a];
    }
}

// ---------------- launch ----------------
extern "C" void kernel_launch(void* const* d_in, const int* in_sizes, int n_in,
                              void* d_out, int out_size) {
    const float* x          = (const float*)d_in[0];
    const float* norm1_g    = (const float*)d_in[1];
    const float* norm1_b    = (const float*)d_in[2];
    const float* qkv_w      = (const float*)d_in[3];
    const float* qkv_b      = (const float*)d_in[4];
    const float* bias_table = (const float*)d_in[5];
    const float* proj_w     = (const float*)d_in[6];
    const float* proj_b     = (const float*)d_in[7];
    const float* norm2_g    = (const float*)d_in[8];
    const float* norm2_b    = (const float*)d_in[9];
    const float* fc1_w      = (const float*)d_in[10];
    const float* fc1_b      = (const float*)d_in[11];
    const float* fc2_w      = (const float*)d_in[12];
    const float* fc2_b      = (const float*)d_in[13];
    float* out = (float*)d_out;

    float *hw, *qkv, *attn, *fc1, *ln2, *x2;
    cudaGetSymbolAddress((void**)&hw,   g_hw);
    cudaGetSymbolAddress((void**)&qkv,  g_qkv);
    cudaGetSymbolAddress((void**)&attn, g_attn);
    cudaGetSymbolAddress((void**)&fc1,  g_fc1);
    cudaGetSymbolAddress((void**)&ln2,  g_ln2);
    cudaGetSymbolAddress((void**)&x2,   g_x2);
    float* projp;
    cudaGetSymbolAddress((void**)&projp, g_proj);

    const int ATTN_SMEM = (3 * NTOK * QKS + NTOK * NTOK) * 4;  // 139968 B
    cudaFuncSetAttribute(attn_kernel, cudaFuncAttributeMaxDynamicSharedMemorySize, ATTN_SMEM);

    // 1) LN1 + window partition
    ln1_kernel<<<MTOK, 256>>>(x, norm1_g, norm1_b);

    // 2) QKV gemm: [115200,256] x [768,256]^T
    sgemm_kernel<false, false><<<dim3(768 / 128, MTOK / 128), 256>>>(
        hw, qkv_w, qkv_b, nullptr, qkv, MTOK, 3 * DIM, DIM);

    // 3) windowed attention (800 windows x 8 heads)
    attn_kernel<<<dim3(NW * (BATCH * NLON), HEADS), 256, ATTN_SMEM>>>(bias_table);

    // 4) proj gemm: [115200,256] x [256,256]^T
    sgemm_kernel<false, false><<<dim3(DIM / 128, MTOK / 128), 256>>>(
        attn, proj_w, proj_b, nullptr, projp, MTOK, DIM, DIM);

    // 5) window reverse + residual + LN2
    add_ln2_kernel<<<MTOK, 256>>>(x, norm2_g, norm2_b);

    // 6) fc1 gemm + exact gelu: [115200,256] x [1024,256]^T
    sgemm_kernel<true, false><<<dim3(HID / 128, MTOK / 128), 256>>>(
        ln2, fc1_w, fc1_b, nullptr, fc1, MTOK, HID, DIM);

    // 7) fc2 gemm + residual: [115200,1024] x [256,1024]^T -> out
    sgemm_kernel<false, true><<<dim3(DIM / 128, MTOK / 128), 256>>>(
        fc1, fc2_w, fc2_b, x2, out, MTOK, DIM, HID);
}

// round 2
// speedup vs baseline: 2.0255x; 2.0255x over previous
#include <cuda_runtime.h>
#include <math.h>
#include <stdint.h>

// ---------------- problem constants ----------------
#define DIM   256
#define HEADS 8
#define HD    32
#define PL    8
#define LAT   60
#define LON   120
#define WPL   2
#define WLAT  6
#define WLON  12
#define NTOK  144            // tokens per window
#define NPL   (PL/WPL)       // 4
#define NLAT  (LAT/WLAT)     // 10
#define NLON  (LON/WLON)     // 10
#define NW    (NPL*NLAT)     // 40 window types
#define BATCH 2
#define LTOK  (PL*LAT*LON)   // 57600
#define MTOK  (BATCH*LTOK)   // 115200
#define HID   1024
#define QKS   33             // padded stride for q/k/v in smem

// ---------------- scratch (static device globals; no allocation) ----------------
__device__ float g_hw  [(size_t)MTOK*DIM];     // LN1 output, window-ordered
__device__ float g_qkv [(size_t)MTOK*3*DIM];   // window-ordered qkv
__device__ float g_attn[(size_t)MTOK*DIM];     // window-ordered attention output
__device__ float g_proj[(size_t)MTOK*DIM];     // window-ordered proj output
__device__ float g_x2  [(size_t)MTOK*DIM];     // token-ordered residual (x + attn branch)
__device__ float g_ln2 [(size_t)MTOK*DIM];     // token-ordered LN2 output
__device__ float g_fc1 [(size_t)MTOK*HID];     // token-ordered fc1+gelu output

// ---------------- helpers ----------------
__device__ __forceinline__ int win_index(int t) {
    int b   = t / LTOK;
    int rem = t - b * LTOK;
    int pl  = rem / (LAT * LON);
    int r2  = rem - pl * (LAT * LON);
    int lat = r2 / LON;
    int lon = r2 - lat * LON;
    int np = pl / WPL,  ip = pl - np * WPL;
    int nl = lat / WLAT, il = lat - nl * WLAT;
    int no = lon / WLON, io = lon - no * WLON;
    int wb = b * NLON + no;
    int w  = np * NLAT + nl;
    int n  = (ip * WLAT + il) * WLON + io;
    return (wb * NW + w) * NTOK + n;
}

__device__ __forceinline__ void blk_reduce2(float& a, float& b) {
    #pragma unroll
    for (int o = 16; o > 0; o >>= 1) {
        a += __shfl_xor_sync(0xffffffffu, a, o);
        b += __shfl_xor_sync(0xffffffffu, b, o);
    }
    __shared__ float sa[8], sb[8];
    int w = threadIdx.x >> 5, l = threadIdx.x & 31;
    if (l == 0) { sa[w] = a; sb[w] = b; }
    __syncthreads();
    float ta = 0.f, tb = 0.f;
    #pragma unroll
    for (int i = 0; i < 8; i++) { ta += sa[i]; tb += sb[i]; }
    a = ta; b = tb;
}

// ---------------- LN1 (+ window partition scatter) ----------------
__global__ void ln1_kernel(const float* __restrict__ x,
                           const float* __restrict__ g,
                           const float* __restrict__ b) {
    int t = blockIdx.x, c = threadIdx.x;
    float v = x[(size_t)t * DIM + c];
    float s = v, q = v * v;
    blk_reduce2(s, q);
    float mu  = s * (1.0f / DIM);
    float var = q * (1.0f / DIM) - mu * mu;
    float y = (v - mu) * rsqrtf(fmaxf(var, 0.f) + 1e-5f) * g[c] + b[c];
    g_hw[(size_t)win_index(t) * DIM + c] = y;
}

// ---------------- residual add (window reverse gather) + LN2 ----------------
__global__ void add_ln2_kernel(const float* __restrict__ x,
                               const float* __restrict__ g,
                               const float* __restrict__ b) {
    int t = blockIdx.x, c = threadIdx.x;
    float v = x[(size_t)t * DIM + c] + g_proj[(size_t)win_index(t) * DIM + c];
    g_x2[(size_t)t * DIM + c] = v;
    float s = v, q = v * v;
    blk_reduce2(s, q);
    float mu  = s * (1.0f / DIM);
    float var = q * (1.0f / DIM) - mu * mu;
    g_ln2[(size_t)t * DIM + c] =
        (v - mu) * rsqrtf(fmaxf(var, 0.f) + 1e-5f) * g[c] + b[c];
}

// ---------------- tf32 tensor-core GEMM ----------------
// C[M,N] = A[M,K] @ W[N,K]^T + bias (+gelu) (+residual)
// BM=BN=128, BK=32, 256 threads (8 warps, 4x2), mma.m16n8k8.tf32,
// XOR-swizzled smem, 2-stage cp.async double buffering.
#define BM 128
#define BN 128
#define BK 32

__device__ __forceinline__ uint32_t f2tf32(float f) {
    uint32_t u;
    asm("cvt.rna.tf32.f32 %0, %1;" : "=r"(u) : "f"(f));
    return u;
}

__device__ __forceinline__ void cp16(void* smem_dst, const void* gmem_src) {
    uint32_t s = (uint32_t)__cvta_generic_to_shared(smem_dst);
    asm volatile("cp.async.cg.shared.global [%0], [%1], 16;\n" :: "r"(s), "l"(gmem_src));
}

template<bool GELU, bool RES>
__global__ __launch_bounds__(256)
void tgemm_kernel(const float* __restrict__ A,
                  const float* __restrict__ W,
                  const float* __restrict__ bias,
                  const float* __restrict__ res,
                  float* __restrict__ C,
                  int M, int N, int K) {
    __shared__ float sA[2][BM * BK];
    __shared__ float sB[2][BN * BK];

    int tid  = threadIdx.x;
    int bm   = blockIdx.y * BM;
    int bn   = blockIdx.x * BN;
    int warp = tid >> 5, lane = tid & 31;
    int wm = (warp & 3) * 32;     // warp row offset within tile
    int wn = (warp >> 2) * 64;    // warp col offset within tile
    int gID = lane >> 2;          // group id 0..7
    int tig = lane & 3;           // thread-in-group 0..3

    float acc[2][8][4];
    #pragma unroll
    for (int mt = 0; mt < 2; mt++)
        #pragma unroll
        for (int nt = 0; nt < 8; nt++)
            #pragma unroll
            for (int i = 0; i < 4; i++) acc[mt][nt][i] = 0.f;

    int niter = K / BK;

    // stage loader: 128 rows x 8 float4-chunks per operand, 256 threads x 4 chunks
    auto load_stage = [&](int s, int k0) {
        #pragma unroll
        for (int r = 0; r < 4; r++) {
            int idx = tid + r * 256;           // 0..1023
            int row = idx >> 3;
            int kq  = idx & 7;
            int sw  = row * BK + ((kq ^ (row & 7)) << 2);
            cp16(&sA[s][sw], &A[(size_t)(bm + row) * K + k0 + kq * 4]);
            cp16(&sB[s][sw], &W[(size_t)(bn + row) * K + k0 + kq * 4]);
        }
        asm volatile("cp.async.commit_group;\n");
    };

    load_stage(0, 0);

    for (int it = 0; it < niter; it++) {
        int cur = it & 1;
        if (it + 1 < niter) {
            load_stage(cur ^ 1, (it + 1) * BK);
            asm volatile("cp.async.wait_group 1;\n");
        } else {
            asm volatile("cp.async.wait_group 0;\n");
        }
        __syncthreads();

        const float* cA = sA[cur];
        const float* cB = sB[cur];

        #pragma unroll
        for (int ks = 0; ks < 4; ks++) {
            int ks2 = ks * 2;
            // A fragments: 2 m-tiles x 4 regs
            uint32_t af[2][4];
            #pragma unroll
            for (int mt = 0; mt < 2; mt++) {
                int r0 = wm + mt * 16 + gID;
                int r1 = r0 + 8;
                int s00 = r0 * BK + (((ks2)     ^ (r0 & 7)) << 2) + tig;
                int s02 = r0 * BK + (((ks2 + 1) ^ (r0 & 7)) << 2) + tig;
                int s10 = r1 * BK + (((ks2)     ^ (r1 & 7)) << 2) + tig;
                int s12 = r1 * BK + (((ks2 + 1) ^ (r1 & 7)) << 2) + tig;
                af[mt][0] = f2tf32(cA[s00]);
                af[mt][1] = f2tf32(cA[s10]);
                af[mt][2] = f2tf32(cA[s02]);
                af[mt][3] = f2tf32(cA[s12]);
            }
            // B fragments: 8 n-tiles x 2 regs
            uint32_t bf[8][2];
            #pragma unroll
            for (int nt = 0; nt < 8; nt++) {
                int n = wn + nt * 8 + gID;
                int s0 = n * BK + (((ks2)     ^ (n & 7)) << 2) + tig;
                int s1 = n * BK + (((ks2 + 1) ^ (n & 7)) << 2) + tig;
                bf[nt][0] = f2tf32(cB[s0]);
                bf[nt][1] = f2tf32(cB[s1]);
            }
            #pragma unroll
            for (int mt = 0; mt < 2; mt++)
                #pragma unroll
                for (int nt = 0; nt < 8; nt++) {
                    asm volatile(
                        "mma.sync.aligned.m16n8k8.row.col.f32.tf32.tf32.f32 "
                        "{%0,%1,%2,%3}, {%4,%5,%6,%7}, {%8,%9}, {%0,%1,%2,%3};"
                        : "+f"(acc[mt][nt][0]), "+f"(acc[mt][nt][1]),
                          "+f"(acc[mt][nt][2]), "+f"(acc[mt][nt][3])
                        : "r"(af[mt][0]), "r"(af[mt][1]), "r"(af[mt][2]), "r"(af[mt][3]),
                          "r"(bf[nt][0]), "r"(bf[nt][1]));
                }
        }
        __syncthreads();
    }

    // epilogue
    #pragma unroll
    for (int mt = 0; mt < 2; mt++) {
        int r0 = bm + wm + mt * 16 + gID;
        int r1 = r0 + 8;
        #pragma unroll
        for (int nt = 0; nt < 8; nt++) {
            int c = bn + wn + nt * 8 + tig * 2;
            float b0 = bias[c], b1 = bias[c + 1];
            float v00 = acc[mt][nt][0] + b0;
            float v01 = acc[mt][nt][1] + b1;
            float v10 = acc[mt][nt][2] + b0;
            float v11 = acc[mt][nt][3] + b1;
            if (GELU) {
                v00 = 0.5f * v00 * (1.0f + erff(v00 * 0.70710678118654752f));
                v01 = 0.5f * v01 * (1.0f + erff(v01 * 0.70710678118654752f));
                v10 = 0.5f * v10 * (1.0f + erff(v10 * 0.70710678118654752f));
                v11 = 0.5f * v11 * (1.0f + erff(v11 * 0.70710678118654752f));
            }
            size_t o0 = (size_t)r0 * N + c;
            size_t o1 = (size_t)r1 * N + c;
            if (RES) {
                float2 q0 = *(const float2*)&res[o0];
                float2 q1 = *(const float2*)&res[o1];
                v00 += q0.x; v01 += q0.y; v10 += q1.x; v11 += q1.y;
            }
            *(float2*)&C[o0] = make_float2(v00, v01);
            *(float2*)&C[o1] = make_float2(v10, v11);
        }
    }
}

// ---------------- windowed attention with earth position bias ----------------
__global__ void attn_kernel(const float* __restrict__ bias_table) {
    extern __shared__ float sm[];
    float* sq = sm;
    float* sk = sq + NTOK * QKS;
    float* sv = sk + NTOK * QKS;
    float* sp = sv + NTOK * QKS;   // [144][144]

    int wg = blockIdx.x;
    int h  = blockIdx.y;
    int wt = wg % NW;
    int tid = threadIdx.x;
    size_t base = (size_t)wg * NTOK;
    const float scale = 0.17677669529663687f;

    for (int idx = tid; idx < NTOK * HD; idx += 256) {
        int n = idx >> 5, e = idx & 31;
        size_t toff = (base + n) * (size_t)(3 * DIM);
        sq[n * QKS + e] = g_qkv[toff +            h * HD + e] * scale;
        sk[n * QKS + e] = g_qkv[toff + DIM     +  h * HD + e];
        sv[n * QKS + e] = g_qkv[toff + 2 * DIM +  h * HD + e];
    }
    __syncthreads();

    int ty = tid >> 4, tx = tid & 15;
    float acc[9][9];
    #pragma unroll
    for (int a = 0; a < 9; a++)
        #pragma unroll
        for (int b = 0; b < 9; b++) acc[a][b] = 0.f;

    #pragma unroll 4
    for (int e = 0; e < HD; e++) {
        float rq[9], rk[9];
        #pragma unroll
        for (int a = 0; a < 9; a++) rq[a] = sq[(ty + 16 * a) * QKS + e];
        #pragma unroll
        for (int b = 0; b < 9; b++) rk[b] = sk[(tx + 16 * b) * QKS + e];
        #pragma unroll
        for (int a = 0; a < 9; a++)
            #pragma unroll
            for (int b = 0; b < 9; b++)
                acc[a][b] += rq[a] * rk[b];
    }

    #pragma unroll
    for (int a = 0; a < 9; a++) {
        int i = ty + 16 * a;
        int ipl = i / 72, ilat = (i / 12) % 6, ilon = i % 12;
        #pragma unroll
        for (int b = 0; b < 9; b++) {
            int j = tx + 16 * b;
            int jpl = j / 72, jlat = (j / 12) % 6, jlon = j % 12;
            int bidx = (ipl + jpl * 2) * 828 + (ilat + jlat * 6) * 23 + (ilon - jlon + 11);
            float bv = bias_table[((size_t)bidx * NW + wt) * HEADS + h];
            sp[i * NTOK + j] = acc[a][b] + bv;
        }
    }
    __syncthreads();

    int warp = tid >> 5, lane = tid & 31;
    for (int r = warp; r < NTOK; r += 8) {
        float mx = -1e30f;
        for (int j = lane; j < NTOK; j += 32) mx = fmaxf(mx, sp[r * NTOK + j]);
        #pragma unroll
        for (int o = 16; o > 0; o >>= 1) mx = fmaxf(mx, __shfl_xor_sync(0xffffffffu, mx, o));
        float sum = 0.f;
        for (int j = lane; j < NTOK; j += 32) {
            float p = __expf(sp[r * NTOK + j] - mx);
            sp[r * NTOK + j] = p;
            sum += p;
        }
        #pragma unroll
        for (int o = 16; o > 0; o >>= 1) sum += __shfl_xor_sync(0xffffffffu, sum, o);
        float inv = 1.0f / sum;
        for (int j = lane; j < NTOK; j += 32) sp[r * NTOK + j] *= inv;
    }
    __syncthreads();

    float o0[9], o1[9];
    #pragma unroll
    for (int a = 0; a < 9; a++) { o0[a] = 0.f; o1[a] = 0.f; }
    for (int j = 0; j < NTOK; j++) {
        float v0 = sv[j * QKS + tx * 2];
        float v1 = sv[j * QKS + tx * 2 + 1];
        #pragma unroll
        for (int a = 0; a < 9; a++) {
            float p = sp[(ty + 16 * a) * NTOK + j];
            o0[a] += p * v0;
            o1[a] += p * v1;
        }
    }
    #pragma unroll
    for (int a = 0; a < 9; a++) {
        int n = ty + 16 * a;
        size_t off = (base + n) * (size_t)DIM + h * HD + tx * 2;
        g_attn[off]     = o0[a];
        g_attn[off + 1] = o1[a];
    }
}

// ---------------- launch ----------------
extern "C" void kernel_launch(void* const* d_in, const int* in_sizes, int n_in,
                              void* d_out, int out_size) {
    const float* x          = (const float*)d_in[0];
    const float* norm1_g    = (const float*)d_in[1];
    const float* norm1_b    = (const float*)d_in[2];
    const float* qkv_w      = (const float*)d_in[3];
    const float* qkv_b      = (const float*)d_in[4];
    const float* bias_table = (const float*)d_in[5];
    const float* proj_w     = (const float*)d_in[6];
    const float* proj_b     = (const float*)d_in[7];
    const float* norm2_g    = (const float*)d_in[8];
    const float* norm2_b    = (const float*)d_in[9];
    const float* fc1_w      = (const float*)d_in[10];
    const float* fc1_b      = (const float*)d_in[11];
    const float* fc2_w      = (const float*)d_in[12];
    const float* fc2_b      = (const float*)d_in[13];
    float* out = (float*)d_out;

    float *hw, *qkv, *attn, *fc1, *ln2, *x2, *projp;
    cudaGetSymbolAddress((void**)&hw,    g_hw);
    cudaGetSymbolAddress((void**)&qkv,   g_qkv);
    cudaGetSymbolAddress((void**)&attn,  g_attn);
    cudaGetSymbolAddress((void**)&fc1,   g_fc1);
    cudaGetSymbolAddress((void**)&ln2,   g_ln2);
    cudaGetSymbolAddress((void**)&x2,    g_x2);
    cudaGetSymbolAddress((void**)&projp, g_proj);

    const int ATTN_SMEM = (3 * NTOK * QKS + NTOK * NTOK) * 4;  // 139968 B
    cudaFuncSetAttribute(attn_kernel, cudaFuncAttributeMaxDynamicSharedMemorySize, ATTN_SMEM);

    // 1) LN1 + window partition
    ln1_kernel<<<MTOK, 256>>>(x, norm1_g, norm1_b);

    // 2) QKV gemm: [115200,256] x [768,256]^T
    tgemm_kernel<false, false><<<dim3(768 / BN, MTOK / BM), 256>>>(
        hw, qkv_w, qkv_b, nullptr, qkv, MTOK, 3 * DIM, DIM);

    // 3) windowed attention (800 windows x 8 heads)
    attn_kernel<<<dim3(NW * (BATCH * NLON), HEADS), 256, ATTN_SMEM>>>(bias_table);

    // 4) proj gemm: [115200,256] x [256,256]^T
    tgemm_kernel<false, false><<<dim3(DIM / BN, MTOK / BM), 256>>>(
        attn, proj_w, proj_b, nullptr, projp, MTOK, DIM, DIM);

    // 5) window reverse + residual + LN2
    add_ln2_kernel<<<MTOK, 256>>>(x, norm2_g, norm2_b);

    // 6) fc1 gemm + exact gelu: [115200,256] x [1024,256]^T
    tgemm_kernel<true, false><<<dim3(HID / BN, MTOK / BM), 256>>>(
        ln2, fc1_w, fc1_b, nullptr, fc1, MTOK, HID, DIM);

    // 7) fc2 gemm + residual: [115200,1024] x [256,1024]^T -> out
    tgemm_kernel<false, true><<<dim3(DIM / BN, MTOK / BM), 256>>>(
        fc1, fc2_w, fc2_b, x2, out, MTOK, DIM, HID);
}

// round 3
// speedup vs baseline: 3.0856x; 1.5233x over previous
#include <cuda_runtime.h>
#include <math.h>
#include <stdint.h>

// ---------------- problem constants ----------------
#define DIM   256
#define HEADS 8
#define HD    32
#define PL    8
#define LAT   60
#define LON   120
#define WPL   2
#define WLAT  6
#define WLON  12
#define NTOK  144
#define NPL   (PL/WPL)
#define NLAT  (LAT/WLAT)
#define NLON  (LON/WLON)
#define NW    (NPL*NLAT)     // 40
#define BATCH 2
#define LTOK  (PL*LAT*LON)   // 57600
#define MTOK  (BATCH*LTOK)   // 115200
#define HID   1024

// ---------------- scratch ----------------
__device__ float g_hw  [(size_t)MTOK*DIM];
__device__ float g_qkv [(size_t)MTOK*3*DIM];
__device__ float g_attn[(size_t)MTOK*DIM];
__device__ float g_proj[(size_t)MTOK*DIM];
__device__ float g_x2  [(size_t)MTOK*DIM];
__device__ float g_ln2 [(size_t)MTOK*DIM];
__device__ float g_fc1 [(size_t)MTOK*HID];

// ---------------- helpers ----------------
__device__ __forceinline__ int win_index(int t) {
    int b   = t / LTOK;
    int rem = t - b * LTOK;
    int pl  = rem / (LAT * LON);
    int r2  = rem - pl * (LAT * LON);
    int lat = r2 / LON;
    int lon = r2 - lat * LON;
    int np = pl / WPL,  ip = pl - np * WPL;
    int nl = lat / WLAT, il = lat - nl * WLAT;
    int no = lon / WLON, io = lon - no * WLON;
    int wb = b * NLON + no;
    int w  = np * NLAT + nl;
    int n  = (ip * WLAT + il) * WLON + io;
    return (wb * NW + w) * NTOK + n;
}

__device__ __forceinline__ void blk_reduce2(float& a, float& b) {
    #pragma unroll
    for (int o = 16; o > 0; o >>= 1) {
        a += __shfl_xor_sync(0xffffffffu, a, o);
        b += __shfl_xor_sync(0xffffffffu, b, o);
    }
    __shared__ float sa[8], sb[8];
    int w = threadIdx.x >> 5, l = threadIdx.x & 31;
    if (l == 0) { sa[w] = a; sb[w] = b; }
    __syncthreads();
    float ta = 0.f, tb = 0.f;
    #pragma unroll
    for (int i = 0; i < 8; i++) { ta += sa[i]; tb += sb[i]; }
    a = ta; b = tb;
}

__device__ __forceinline__ uint32_t f2tf32(float f) {
    uint32_t u;
    asm("cvt.rna.tf32.f32 %0, %1;" : "=r"(u) : "f"(f));
    return u;
}
__device__ __forceinline__ float tf32r(float f) { return __uint_as_float(f2tf32(f)); }

// ---------------- LN1 (+ window partition scatter) ----------------
__global__ void ln1_kernel(const float* __restrict__ x,
                           const float* __restrict__ g,
                           const float* __restrict__ b) {
    int t = blockIdx.x, c = threadIdx.x;
    float v = x[(size_t)t * DIM + c];
    float s = v, q = v * v;
    blk_reduce2(s, q);
    float mu  = s * (1.0f / DIM);
    float var = q * (1.0f / DIM) - mu * mu;
    float y = (v - mu) * rsqrtf(fmaxf(var, 0.f) + 1e-5f) * g[c] + b[c];
    g_hw[(size_t)win_index(t) * DIM + c] = y;
}

// ---------------- residual add (window reverse gather) + LN2 ----------------
__global__ void add_ln2_kernel(const float* __restrict__ x,
                               const float* __restrict__ g,
                               const float* __restrict__ b) {
    int t = blockIdx.x, c = threadIdx.x;
    float v = x[(size_t)t * DIM + c] + g_proj[(size_t)win_index(t) * DIM + c];
    g_x2[(size_t)t * DIM + c] = v;
    float s = v, q = v * v;
    blk_reduce2(s, q);
    float mu  = s * (1.0f / DIM);
    float var = q * (1.0f / DIM) - mu * mu;
    g_ln2[(size_t)t * DIM + c] =
        (v - mu) * rsqrtf(fmaxf(var, 0.f) + 1e-5f) * g[c] + b[c];
}

// ---------------- tf32 tensor-core GEMM (unchanged from R2) ----------------
#define BM 128
#define BN 128
#define BK 32

__device__ __forceinline__ void cp16(void* smem_dst, const void* gmem_src) {
    uint32_t s = (uint32_t)__cvta_generic_to_shared(smem_dst);
    asm volatile("cp.async.cg.shared.global [%0], [%1], 16;\n" :: "r"(s), "l"(gmem_src));
}

template<bool GELU, bool RES>
__global__ __launch_bounds__(256)
void tgemm_kernel(const float* __restrict__ A,
                  const float* __restrict__ W,
                  const float* __restrict__ bias,
                  const float* __restrict__ res,
                  float* __restrict__ C,
                  int M, int N, int K) {
    __shared__ float sA[2][BM * BK];
    __shared__ float sB[2][BN * BK];

    int tid  = threadIdx.x;
    int bm   = blockIdx.y * BM;
    int bn   = blockIdx.x * BN;
    int warp = tid >> 5, lane = tid & 31;
    int wm = (warp & 3) * 32;
    int wn = (warp >> 2) * 64;
    int gID = lane >> 2;
    int tig = lane & 3;

    float acc[2][8][4];
    #pragma unroll
    for (int mt = 0; mt < 2; mt++)
        #pragma unroll
        for (int nt = 0; nt < 8; nt++)
            #pragma unroll
            for (int i = 0; i < 4; i++) acc[mt][nt][i] = 0.f;

    int niter = K / BK;

    auto load_stage = [&](int s, int k0) {
        #pragma unroll
        for (int r = 0; r < 4; r++) {
            int idx = tid + r * 256;
            int row = idx >> 3;
            int kq  = idx & 7;
            int sw  = row * BK + ((kq ^ (row & 7)) << 2);
            cp16(&sA[s][sw], &A[(size_t)(bm + row) * K + k0 + kq * 4]);
            cp16(&sB[s][sw], &W[(size_t)(bn + row) * K + k0 + kq * 4]);
        }
        asm volatile("cp.async.commit_group;\n");
    };

    load_stage(0, 0);

    for (int it = 0; it < niter; it++) {
        int cur = it & 1;
        if (it + 1 < niter) {
            load_stage(cur ^ 1, (it + 1) * BK);
            asm volatile("cp.async.wait_group 1;\n");
        } else {
            asm volatile("cp.async.wait_group 0;\n");
        }
        __syncthreads();

        const float* cA = sA[cur];
        const float* cB = sB[cur];

        #pragma unroll
        for (int ks = 0; ks < 4; ks++) {
            int ks2 = ks * 2;
            uint32_t af[2][4];
            #pragma unroll
            for (int mt = 0; mt < 2; mt++) {
                int r0 = wm + mt * 16 + gID;
                int r1 = r0 + 8;
                int s00 = r0 * BK + (((ks2)     ^ (r0 & 7)) << 2) + tig;
                int s02 = r0 * BK + (((ks2 + 1) ^ (r0 & 7)) << 2) + tig;
                int s10 = r1 * BK + (((ks2)     ^ (r1 & 7)) << 2) + tig;
                int s12 = r1 * BK + (((ks2 + 1) ^ (r1 & 7)) << 2) + tig;
                af[mt][0] = f2tf32(cA[s00]);
                af[mt][1] = f2tf32(cA[s10]);
                af[mt][2] = f2tf32(cA[s02]);
                af[mt][3] = f2tf32(cA[s12]);
            }
            uint32_t bf[8][2];
            #pragma unroll
            for (int nt = 0; nt < 8; nt++) {
                int n = wn + nt * 8 + gID;
                int s0 = n * BK + (((ks2)     ^ (n & 7)) << 2) + tig;
                int s1 = n * BK + (((ks2 + 1) ^ (n & 7)) << 2) + tig;
                bf[nt][0] = f2tf32(cB[s0]);
                bf[nt][1] = f2tf32(cB[s1]);
            }
            #pragma unroll
            for (int mt = 0; mt < 2; mt++)
                #pragma unroll
                for (int nt = 0; nt < 8; nt++) {
                    asm volatile(
                        "mma.sync.aligned.m16n8k8.row.col.f32.tf32.tf32.f32 "
                        "{%0,%1,%2,%3}, {%4,%5,%6,%7}, {%8,%9}, {%0,%1,%2,%3};"
                        : "+f"(acc[mt][nt][0]), "+f"(acc[mt][nt][1]),
                          "+f"(acc[mt][nt][2]), "+f"(acc[mt][nt][3])
                        : "r"(af[mt][0]), "r"(af[mt][1]), "r"(af[mt][2]), "r"(af[mt][3]),
                          "r"(bf[nt][0]), "r"(bf[nt][1]));
                }
        }
        __syncthreads();
    }

    #pragma unroll
    for (int mt = 0; mt < 2; mt++) {
        int r0 = bm + wm + mt * 16 + gID;
        int r1 = r0 + 8;
        #pragma unroll
        for (int nt = 0; nt < 8; nt++) {
            int c = bn + wn + nt * 8 + tig * 2;
            float b0 = bias[c], b1 = bias[c + 1];
            float v00 = acc[mt][nt][0] + b0;
            float v01 = acc[mt][nt][1] + b1;
            float v10 = acc[mt][nt][2] + b0;
            float v11 = acc[mt][nt][3] + b1;
            if (GELU) {
                v00 = 0.5f * v00 * (1.0f + erff(v00 * 0.70710678118654752f));
                v01 = 0.5f * v01 * (1.0f + erff(v01 * 0.70710678118654752f));
                v10 = 0.5f * v10 * (1.0f + erff(v10 * 0.70710678118654752f));
                v11 = 0.5f * v11 * (1.0f + erff(v11 * 0.70710678118654752f));
            }
            size_t o0 = (size_t)r0 * N + c;
            size_t o1 = (size_t)r1 * N + c;
            if (RES) {
                float2 q0 = *(const float2*)&res[o0];
                float2 q1 = *(const float2*)&res[o1];
                v00 += q0.x; v01 += q0.y; v10 += q1.x; v11 += q1.y;
            }
            *(float2*)&C[o0] = make_float2(v00, v01);
            *(float2*)&C[o1] = make_float2(v10, v11);
        }
    }
}

// ---------------- tensor-core windowed attention ----------------
// block = (window, head), 288 threads = 9 warps, warp w owns query rows [16w,16w+16)
#define QKST 36     // Q/K smem row stride (floats)
#define VST  40     // V smem row stride
#define PST  148    // P staging row stride
#define TBL  3312   // bias table rows

// smem float counts
#define SQ_OFF   0
#define SK_OFF   (NTOK*QKST)                 // 5184
#define SV_OFF   (SK_OFF + NTOK*QKST)        // 10368
#define SP_OFF   (SV_OFF + NTOK*VST)         // 16128
#define SB_OFF   (SP_OFF + 9*16*PST)         // 37440
#define SI_OFF   (SB_OFF + TBL)              // 40752  (ri[144], cj[144] as int)
#define ATTN_SMEM_FLOATS (SI_OFF + 288)
#define ATTN_SMEM_BYTES  (ATTN_SMEM_FLOATS*4)

__global__ __launch_bounds__(288, 1)
void attn_kernel(const float* __restrict__ bias_table) {
    extern __shared__ float sm[];
    float* sq = sm + SQ_OFF;
    float* sk = sm + SK_OFF;
    float* sv = sm + SV_OFF;
    float* sp = sm + SP_OFF;
    float* sb = sm + SB_OFF;
    int*   sri = (int*)(sm + SI_OFF);
    int*   scj = sri + NTOK;

    int wg = blockIdx.x;
    int h  = blockIdx.y;
    int wt = wg % NW;
    int tid = threadIdx.x;
    size_t base = (size_t)wg * NTOK;
    const float scale = 0.17677669529663687f;

    // separable bias index tables
    if (tid < NTOK) {
        int i = tid;
        sri[i] = (i / 72) * 828 + ((i / 12) % 6) * 23 + (i % 12);
    } else {
        int j = tid - NTOK;
        scj[j] = (j / 72) * 1656 + ((j / 12) % 6) * 138 + (11 - (j % 12));
    }

    // gather bias slice for (wt, h): sb[bidx] = bias_table[bidx*320 + wt*8 + h]
    {
        int off = wt * HEADS + h;
        for (int idx = tid; idx < TBL; idx += 288)
            sb[idx] = __ldg(&bias_table[(size_t)idx * (NW * HEADS) + off]);
    }

    // load q (scaled), k, v — tf32-rounded at store
    for (int idx = tid; idx < NTOK * 8; idx += 288) {
        int n = idx >> 3, e4 = (idx & 7) * 4;
        size_t toff = (base + n) * (size_t)(3 * DIM) + h * HD + e4;
        float4 q4 = *(const float4*)&g_qkv[toff];
        float4 k4 = *(const float4*)&g_qkv[toff + DIM];
        float4 v4 = *(const float4*)&g_qkv[toff + 2 * DIM];
        *(float4*)&sq[n * QKST + e4] = make_float4(tf32r(q4.x * scale), tf32r(q4.y * scale),
                                                   tf32r(q4.z * scale), tf32r(q4.w * scale));
        *(float4*)&sk[n * QKST + e4] = make_float4(tf32r(k4.x), tf32r(k4.y), tf32r(k4.z), tf32r(k4.w));
        *(float4*)&sv[n * VST  + e4] = make_float4(tf32r(v4.x), tf32r(v4.y), tf32r(v4.z), tf32r(v4.w));
    }
    __syncthreads();

    int warp = tid >> 5, lane = tid & 31;
    int gID = lane >> 2, tig = lane & 3;
    int r0 = warp * 16 + gID;     // global query row
    int r1 = r0 + 8;

    // ---- QK^T: 18 n-tiles x 4 k-steps ----
    float acc[18][4];
    #pragma unroll
    for (int nt = 0; nt < 18; nt++)
        #pragma unroll
        for (int i = 0; i < 4; i++) acc[nt][i] = 0.f;

    #pragma unroll
    for (int ks = 0; ks < 4; ks++) {
        int k0 = ks * 8;
        uint32_t a0 = __float_as_uint(sq[r0 * QKST + k0 + tig]);
        uint32_t a1 = __float_as_uint(sq[r1 * QKST + k0 + tig]);
        uint32_t a2 = __float_as_uint(sq[r0 * QKST + k0 + tig + 4]);
        uint32_t a3 = __float_as_uint(sq[r1 * QKST + k0 + tig + 4]);
        #pragma unroll
        for (int nt = 0; nt < 18; nt++) {
            int n = nt * 8 + gID;
            uint32_t b0 = __float_as_uint(sk[n * QKST + k0 + tig]);
            uint32_t b1 = __float_as_uint(sk[n * QKST + k0 + tig + 4]);
            asm volatile(
                "mma.sync.aligned.m16n8k8.row.col.f32.tf32.tf32.f32 "
                "{%0,%1,%2,%3}, {%4,%5,%6,%7}, {%8,%9}, {%0,%1,%2,%3};"
                : "+f"(acc[nt][0]), "+f"(acc[nt][1]), "+f"(acc[nt][2]), "+f"(acc[nt][3])
                : "r"(a0), "r"(a1), "r"(a2), "r"(a3), "r"(b0), "r"(b1));
        }
    }

    // ---- bias add + row max ----
    int ri0 = sri[r0], ri1 = sri[r1];
    float mx0 = -1e30f, mx1 = -1e30f;
    #pragma unroll
    for (int nt = 0; nt < 18; nt++) {
        int j0 = nt * 8 + 2 * tig, j1 = j0 + 1;
        int c0 = scj[j0], c1 = scj[j1];
        acc[nt][0] += sb[ri0 + c0];
        acc[nt][1] += sb[ri0 + c1];
        acc[nt][2] += sb[ri1 + c0];
        acc[nt][3] += sb[ri1 + c1];
        mx0 = fmaxf(mx0, fmaxf(acc[nt][0], acc[nt][1]));
        mx1 = fmaxf(mx1, fmaxf(acc[nt][2], acc[nt][3]));
    }
    mx0 = fmaxf(mx0, __shfl_xor_sync(0xffffffffu, mx0, 1));
    mx0 = fmaxf(mx0, __shfl_xor_sync(0xffffffffu, mx0, 2));
    mx1 = fmaxf(mx1, __shfl_xor_sync(0xffffffffu, mx1, 1));
    mx1 = fmaxf(mx1, __shfl_xor_sync(0xffffffffu, mx1, 2));

    // ---- exp + sum ----
    float s0 = 0.f, s1 = 0.f;
    #pragma unroll
    for (int nt = 0; nt < 18; nt++) {
        acc[nt][0] = __expf(acc[nt][0] - mx0);
        acc[nt][1] = __expf(acc[nt][1] - mx0);
        acc[nt][2] = __expf(acc[nt][2] - mx1);
        acc[nt][3] = __expf(acc[nt][3] - mx1);
        s0 += acc[nt][0] + acc[nt][1];
        s1 += acc[nt][2] + acc[nt][3];
    }
    s0 += __shfl_xor_sync(0xffffffffu, s0, 1);
    s0 += __shfl_xor_sync(0xffffffffu, s0, 2);
    s1 += __shfl_xor_sync(0xffffffffu, s1, 1);
    s1 += __shfl_xor_sync(0xffffffffu, s1, 2);
    float inv0 = 1.0f / s0, inv1 = 1.0f / s1;

    // ---- stage P (tf32-rounded) ----
    float* pw = sp + warp * 16 * PST;
    #pragma unroll
    for (int nt = 0; nt < 18; nt++) {
        int c = nt * 8 + 2 * tig;
        *(float2*)&pw[gID * PST + c]       = make_float2(tf32r(acc[nt][0] * inv0), tf32r(acc[nt][1] * inv0));
        *(float2*)&pw[(gID + 8) * PST + c] = make_float2(tf32r(acc[nt][2] * inv1), tf32r(acc[nt][3] * inv1));
    }
    __syncwarp();

    // ---- PV: out[16,32] = P[16,144] x V[144,32] ----
    float oacc[4][4];
    #pragma unroll
    for (int nt = 0; nt < 4; nt++)
        #pragma unroll
        for (int i = 0; i < 4; i++) oacc[nt][i] = 0.f;

    #pragma unroll
    for (int ks = 0; ks < 18; ks++) {
        int k0 = ks * 8;
        uint32_t a0 = __float_as_uint(pw[gID * PST + k0 + tig]);
        uint32_t a1 = __float_as_uint(pw[(gID + 8) * PST + k0 + tig]);
        uint32_t a2 = __float_as_uint(pw[gID * PST + k0 + tig + 4]);
        uint32_t a3 = __float_as_uint(pw[(gID + 8) * PST + k0 + tig + 4]);
        #pragma unroll
        for (int nt = 0; nt < 4; nt++) {
            int n = nt * 8 + gID;
            uint32_t b0 = __float_as_uint(sv[(k0 + tig) * VST + n]);
            uint32_t b1 = __float_as_uint(sv[(k0 + tig + 4) * VST + n]);
            asm volatile(
                "mma.sync.aligned.m16n8k8.row.col.f32.tf32.tf32.f32 "
                "{%0,%1,%2,%3}, {%4,%5,%6,%7}, {%8,%9}, {%0,%1,%2,%3};"
                : "+f"(oacc[nt][0]), "+f"(oacc[nt][1]), "+f"(oacc[nt][2]), "+f"(oacc[nt][3])
                : "r"(a0), "r"(a1), "r"(a2), "r"(a3), "r"(b0), "r"(b1));
        }
    }

    // ---- write out ----
    #pragma unroll
    for (int nt = 0; nt < 4; nt++) {
        int c = h * HD + nt * 8 + 2 * tig;
        *(float2*)&g_attn[(base + r0) * (size_t)DIM + c] = make_float2(oacc[nt][0], oacc[nt][1]);
        *(float2*)&g_attn[(base + r1) * (size_t)DIM + c] = make_float2(oacc[nt][2], oacc[nt][3]);
    }
}

// ---------------- launch ----------------
extern "C" void kernel_launch(void* const* d_in, const int* in_sizes, int n_in,
                              void* d_out, int out_size) {
    const float* x          = (const float*)d_in[0];
    const float* norm1_g    = (const float*)d_in[1];
    const float* norm1_b    = (const float*)d_in[2];
    const float* qkv_w      = (const float*)d_in[3];
    const float* qkv_b      = (const float*)d_in[4];
    const float* bias_table = (const float*)d_in[5];
    const float* proj_w     = (const float*)d_in[6];
    const float* proj_b     = (const float*)d_in[7];
    const float* norm2_g    = (const float*)d_in[8];
    const float* norm2_b    = (const float*)d_in[9];
    const float* fc1_w      = (const float*)d_in[10];
    const float* fc1_b      = (const float*)d_in[11];
    const float* fc2_w      = (const float*)d_in[12];
    const float* fc2_b      = (const float*)d_in[13];
    float* out = (float*)d_out;

    float *hw, *qkv, *attn, *fc1, *ln2, *x2, *projp;
    cudaGetSymbolAddress((void**)&hw,    g_hw);
    cudaGetSymbolAddress((void**)&qkv,   g_qkv);
    cudaGetSymbolAddress((void**)&attn,  g_attn);
    cudaGetSymbolAddress((void**)&fc1,   g_fc1);
    cudaGetSymbolAddress((void**)&ln2,   g_ln2);
    cudaGetSymbolAddress((void**)&x2,    g_x2);
    cudaGetSymbolAddress((void**)&projp, g_proj);

    cudaFuncSetAttribute(attn_kernel, cudaFuncAttributeMaxDynamicSharedMemorySize, ATTN_SMEM_BYTES);

    // 1) LN1 + window partition
    ln1_kernel<<<MTOK, 256>>>(x, norm1_g, norm1_b);

    // 2) QKV gemm
    tgemm_kernel<false, false><<<dim3(768 / BN, MTOK / BM), 256>>>(
        hw, qkv_w, qkv_b, nullptr, qkv, MTOK, 3 * DIM, DIM);

    // 3) windowed attention
    attn_kernel<<<dim3(NW * (BATCH * NLON), HEADS), 288, ATTN_SMEM_BYTES>>>(bias_table);

    // 4) proj gemm
    tgemm_kernel<false, false><<<dim3(DIM / BN, MTOK / BM), 256>>>(
        attn, proj_w, proj_b, nullptr, projp, MTOK, DIM, DIM);

    // 5) window reverse + residual + LN2
    add_ln2_kernel<<<MTOK, 256>>>(x, norm2_g, norm2_b);

    // 6) fc1 gemm + exact gelu
    tgemm_kernel<true, false><<<dim3(HID / BN, MTOK / BM), 256>>>(
        ln2, fc1_w, fc1_b, nullptr, fc1, MTOK, HID, DIM);

    // 7) fc2 gemm + residual -> out
    tgemm_kernel<false, true><<<dim3(DIM / BN, MTOK / BM), 256>>>(
        fc1, fc2_w, fc2_b, x2, out, MTOK, DIM, HID);
}

// round 4
// speedup vs baseline: 4.2071x; 1.3635x over previous
#include <cuda_runtime.h>
#include <cuda_bf16.h>
#include <math.h>
#include <stdint.h>

// ---------------- problem constants ----------------
#define DIM   256
#define HEADS 8
#define HD    32
#define PL    8
#define LAT   60
#define LON   120
#define WPL   2
#define WLAT  6
#define WLON  12
#define NTOK  144
#define NPL   (PL/WPL)
#define NLAT  (LAT/WLAT)
#define NLON  (LON/WLON)
#define NW    (NPL*NLAT)     // 40
#define BATCH 2
#define LTOK  (PL*LAT*LON)   // 57600
#define MTOK  (BATCH*LTOK)   // 115200
#define HID   1024

typedef __nv_bfloat16 bf16;

// ---------------- scratch ----------------
__device__ bf16  g_hw  [(size_t)MTOK*DIM];       // LN1 out (bf16, window-ordered)
__device__ float g_qkv [(size_t)MTOK*3*DIM];     // qkv (float, window-ordered)
__device__ bf16  g_attn[(size_t)MTOK*DIM];       // attention out (bf16, window-ordered)
__device__ float g_proj[(size_t)MTOK*DIM];       // proj out (float, window-ordered)
__device__ float g_x2  [(size_t)MTOK*DIM];       // residual (float, token-ordered)
__device__ bf16  g_ln2 [(size_t)MTOK*DIM];       // LN2 out (bf16, token-ordered)
__device__ bf16  g_fc1 [(size_t)MTOK*HID];       // fc1+gelu out (bf16)
// bf16 weight copies
__device__ bf16  g_wqkv [3*DIM*DIM];
__device__ bf16  g_wproj[DIM*DIM];
__device__ bf16  g_wfc1 [HID*DIM];
__device__ bf16  g_wfc2 [DIM*HID];

// ---------------- helpers ----------------
__device__ __forceinline__ int win_index(int t) {
    int b   = t / LTOK;
    int rem = t - b * LTOK;
    int pl  = rem / (LAT * LON);
    int r2  = rem - pl * (LAT * LON);
    int lat = r2 / LON;
    int lon = r2 - lat * LON;
    int np = pl / WPL,  ip = pl - np * WPL;
    int nl = lat / WLAT, il = lat - nl * WLAT;
    int no = lon / WLON, io = lon - no * WLON;
    int wb = b * NLON + no;
    int w  = np * NLAT + nl;
    int n  = (ip * WLAT + il) * WLON + io;
    return (wb * NW + w) * NTOK + n;
}

__device__ __forceinline__ void blk_reduce2(float& a, float& b) {
    #pragma unroll
    for (int o = 16; o > 0; o >>= 1) {
        a += __shfl_xor_sync(0xffffffffu, a, o);
        b += __shfl_xor_sync(0xffffffffu, b, o);
    }
    __shared__ float sa[8], sb[8];
    int w = threadIdx.x >> 5, l = threadIdx.x & 31;
    if (l == 0) { sa[w] = a; sb[w] = b; }
    __syncthreads();
    float ta = 0.f, tb = 0.f;
    #pragma unroll
    for (int i = 0; i < 8; i++) { ta += sa[i]; tb += sb[i]; }
    a = ta; b = tb;
}

__device__ __forceinline__ uint32_t f2tf32(float f) {
    uint32_t u;
    asm("cvt.rna.tf32.f32 %0, %1;" : "=r"(u) : "f"(f));
    return u;
}
__device__ __forceinline__ float tf32r(float f) { return __uint_as_float(f2tf32(f)); }

// ---------------- f32 -> bf16 weight conversion ----------------
__global__ void f2bf_kernel(const float* __restrict__ src, bf16* __restrict__ dst, int n4) {
    int i = blockIdx.x * blockDim.x + threadIdx.x;
    if (i < n4) {
        float4 v = *(const float4*)&src[i * 4];
        __nv_bfloat162 p0 = __floats2bfloat162_rn(v.x, v.y);
        __nv_bfloat162 p1 = __floats2bfloat162_rn(v.z, v.w);
        *(__nv_bfloat162*)&dst[i * 4]     = p0;
        *(__nv_bfloat162*)&dst[i * 4 + 2] = p1;
    }
}

// ---------------- LN1 (+ window partition scatter, bf16 out) ----------------
__global__ void ln1_kernel(const float* __restrict__ x,
                           const float* __restrict__ g,
                           const float* __restrict__ b) {
    int t = blockIdx.x, c = threadIdx.x;
    float v = x[(size_t)t * DIM + c];
    float s = v, q = v * v;
    blk_reduce2(s, q);
    float mu  = s * (1.0f / DIM);
    float var = q * (1.0f / DIM) - mu * mu;
    float y = (v - mu) * rsqrtf(fmaxf(var, 0.f) + 1e-5f) * g[c] + b[c];
    g_hw[(size_t)win_index(t) * DIM + c] = __float2bfloat16(y);
}

// ---------------- residual add + LN2 (bf16 out for fc1) ----------------
__global__ void add_ln2_kernel(const float* __restrict__ x,
                               const float* __restrict__ g,
                               const float* __restrict__ b) {
    int t = blockIdx.x, c = threadIdx.x;
    float v = x[(size_t)t * DIM + c] + g_proj[(size_t)win_index(t) * DIM + c];
    g_x2[(size_t)t * DIM + c] = v;
    float s = v, q = v * v;
    blk_reduce2(s, q);
    float mu  = s * (1.0f / DIM);
    float var = q * (1.0f / DIM) - mu * mu;
    g_ln2[(size_t)t * DIM + c] = __float2bfloat16(
        (v - mu) * rsqrtf(fmaxf(var, 0.f) + 1e-5f) * g[c] + b[c]);
}

// ---------------- bf16 tensor-core GEMM ----------------
// C[M,N] = A[M,K](bf16) @ W[N,K]^T(bf16) + bias (+gelu) (+res)
// BM=BN=128, BK=32, 256 threads (8 warps 4x2), mma.m16n8k16.bf16.f32,
// padded smem stride 40 (conflict-free), 2-stage cp.async.
#define BM 128
#define BN 128
#define BK 32
#define SAS 40   // smem row stride in bf16 units (80 B, 16B-aligned)

__device__ __forceinline__ void cp16(void* smem_dst, const void* gmem_src) {
    uint32_t s = (uint32_t)__cvta_generic_to_shared(smem_dst);
    asm volatile("cp.async.cg.shared.global [%0], [%1], 16;\n" :: "r"(s), "l"(gmem_src));
}

template<bool GELU, bool RES, bool OBF>
__global__ __launch_bounds__(256)
void bgemm_kernel(const bf16* __restrict__ A,
                  const bf16* __restrict__ W,
                  const float* __restrict__ bias,
                  const float* __restrict__ res,
                  void* __restrict__ Cv,
                  int M, int N, int K) {
    __shared__ bf16 sA[2][BM * SAS];
    __shared__ bf16 sB[2][BN * SAS];

    int tid  = threadIdx.x;
    int bm   = blockIdx.y * BM;
    int bn   = blockIdx.x * BN;
    int warp = tid >> 5, lane = tid & 31;
    int wm = (warp & 3) * 32;
    int wn = (warp >> 2) * 64;
    int gID = lane >> 2;
    int tig = lane & 3;

    float acc[2][8][4];
    #pragma unroll
    for (int mt = 0; mt < 2; mt++)
        #pragma unroll
        for (int nt = 0; nt < 8; nt++)
            #pragma unroll
            for (int i = 0; i < 4; i++) acc[mt][nt][i] = 0.f;

    int niter = K / BK;

    // stage: per operand 128 rows x 4 chunks(16B=8 bf16); 512 chunks, 2/thread
    auto load_stage = [&](int s, int k0) {
        #pragma unroll
        for (int r = 0; r < 2; r++) {
            int idx = tid + r * 256;
            int row = idx >> 2;
            int c   = idx & 3;
            cp16(&sA[s][row * SAS + c * 8], &A[(size_t)(bm + row) * K + k0 + c * 8]);
            cp16(&sB[s][row * SAS + c * 8], &W[(size_t)(bn + row) * K + k0 + c * 8]);
        }
        asm volatile("cp.async.commit_group;\n");
    };

    load_stage(0, 0);

    for (int it = 0; it < niter; it++) {
        int cur = it & 1;
        if (it + 1 < niter) {
            load_stage(cur ^ 1, (it + 1) * BK);
            asm volatile("cp.async.wait_group 1;\n");
        } else {
            asm volatile("cp.async.wait_group 0;\n");
        }
        __syncthreads();

        const uint32_t* cA = (const uint32_t*)sA[cur];
        const uint32_t* cB = (const uint32_t*)sB[cur];
        const int HS = SAS / 2;   // 20 words per row

        #pragma unroll
        for (int ks = 0; ks < 2; ks++) {          // two k16 steps
            int kw = ks * 8;                       // word offset along K
            uint32_t af[2][4];
            #pragma unroll
            for (int mt = 0; mt < 2; mt++) {
                int r0 = wm + mt * 16 + gID;
                int r1 = r0 + 8;
                af[mt][0] = cA[r0 * HS + kw + tig];
                af[mt][1] = cA[r1 * HS + kw + tig];
                af[mt][2] = cA[r0 * HS + kw + 4 + tig];
                af[mt][3] = cA[r1 * HS + kw + 4 + tig];
            }
            uint32_t bf[8][2];
            #pragma unroll
            for (int nt = 0; nt < 8; nt++) {
                int n = wn + nt * 8 + gID;
                bf[nt][0] = cB[n * HS + kw + tig];
                bf[nt][1] = cB[n * HS + kw + 4 + tig];
            }
            #pragma unroll
            for (int mt = 0; mt < 2; mt++)
                #pragma unroll
                for (int nt = 0; nt < 8; nt++) {
                    asm volatile(
                        "mma.sync.aligned.m16n8k16.row.col.f32.bf16.bf16.f32 "
                        "{%0,%1,%2,%3}, {%4,%5,%6,%7}, {%8,%9}, {%0,%1,%2,%3};"
                        : "+f"(acc[mt][nt][0]), "+f"(acc[mt][nt][1]),
                          "+f"(acc[mt][nt][2]), "+f"(acc[mt][nt][3])
                        : "r"(af[mt][0]), "r"(af[mt][1]), "r"(af[mt][2]), "r"(af[mt][3]),
                          "r"(bf[nt][0]), "r"(bf[nt][1]));
                }
        }
        __syncthreads();
    }

    // epilogue
    float* Cf = (float*)Cv;
    bf16*  Cb = (bf16*)Cv;
    #pragma unroll
    for (int mt = 0; mt < 2; mt++) {
        int r0 = bm + wm + mt * 16 + gID;
        int r1 = r0 + 8;
        #pragma unroll
        for (int nt = 0; nt < 8; nt++) {
            int c = bn + wn + nt * 8 + tig * 2;
            float b0 = bias[c], b1 = bias[c + 1];
            float v00 = acc[mt][nt][0] + b0;
            float v01 = acc[mt][nt][1] + b1;
            float v10 = acc[mt][nt][2] + b0;
            float v11 = acc[mt][nt][3] + b1;
            if (GELU) {
                v00 = 0.5f * v00 * (1.0f + erff(v00 * 0.70710678118654752f));
                v01 = 0.5f * v01 * (1.0f + erff(v01 * 0.70710678118654752f));
                v10 = 0.5f * v10 * (1.0f + erff(v10 * 0.70710678118654752f));
                v11 = 0.5f * v11 * (1.0f + erff(v11 * 0.70710678118654752f));
            }
            size_t o0 = (size_t)r0 * N + c;
            size_t o1 = (size_t)r1 * N + c;
            if (RES) {
                float2 q0 = *(const float2*)&res[o0];
                float2 q1 = *(const float2*)&res[o1];
                v00 += q0.x; v01 += q0.y; v10 += q1.x; v11 += q1.y;
            }
            if (OBF) {
                *(__nv_bfloat162*)&Cb[o0] = __floats2bfloat162_rn(v00, v01);
                *(__nv_bfloat162*)&Cb[o1] = __floats2bfloat162_rn(v10, v11);
            } else {
                *(float2*)&Cf[o0] = make_float2(v00, v01);
                *(float2*)&Cf[o1] = make_float2(v10, v11);
            }
        }
    }
}

// ---------------- tensor-core windowed attention (tf32, bf16 out) ----------------
#define QKST 36
#define VST  40
#define PST  148
#define TBL  3312

#define SQ_OFF   0
#define SK_OFF   (NTOK*QKST)
#define SV_OFF   (SK_OFF + NTOK*QKST)
#define SP_OFF   (SV_OFF + NTOK*VST)
#define SB_OFF   (SP_OFF + 9*16*PST)
#define SI_OFF   (SB_OFF + TBL)
#define ATTN_SMEM_FLOATS (SI_OFF + 288)
#define ATTN_SMEM_BYTES  (ATTN_SMEM_FLOATS*4)

__global__ __launch_bounds__(288, 1)
void attn_kernel(const float* __restrict__ bias_table) {
    extern __shared__ float sm[];
    float* sq = sm + SQ_OFF;
    float* sk = sm + SK_OFF;
    float* sv = sm + SV_OFF;
    float* sp = sm + SP_OFF;
    float* sb = sm + SB_OFF;
    int*   sri = (int*)(sm + SI_OFF);
    int*   scj = sri + NTOK;

    int wg = blockIdx.x;
    int h  = blockIdx.y;
    int wt = wg % NW;
    int tid = threadIdx.x;
    size_t base = (size_t)wg * NTOK;
    const float scale = 0.17677669529663687f;

    if (tid < NTOK) {
        int i = tid;
        sri[i] = (i / 72) * 828 + ((i / 12) % 6) * 23 + (i % 12);
    } else {
        int j = tid - NTOK;
        scj[j] = (j / 72) * 1656 + ((j / 12) % 6) * 138 + (11 - (j % 12));
    }

    {
        int off = wt * HEADS + h;
        for (int idx = tid; idx < TBL; idx += 288)
            sb[idx] = __ldg(&bias_table[(size_t)idx * (NW * HEADS) + off]);
    }

    for (int idx = tid; idx < NTOK * 8; idx += 288) {
        int n = idx >> 3, e4 = (idx & 7) * 4;
        size_t toff = (base + n) * (size_t)(3 * DIM) + h * HD + e4;
        float4 q4 = *(const float4*)&g_qkv[toff];
        float4 k4 = *(const float4*)&g_qkv[toff + DIM];
        float4 v4 = *(const float4*)&g_qkv[toff + 2 * DIM];
        *(float4*)&sq[n * QKST + e4] = make_float4(tf32r(q4.x * scale), tf32r(q4.y * scale),
                                                   tf32r(q4.z * scale), tf32r(q4.w * scale));
        *(float4*)&sk[n * QKST + e4] = make_float4(tf32r(k4.x), tf32r(k4.y), tf32r(k4.z), tf32r(k4.w));
        *(float4*)&sv[n * VST  + e4] = make_float4(tf32r(v4.x), tf32r(v4.y), tf32r(v4.z), tf32r(v4.w));
    }
    __syncthreads();

    int warp = tid >> 5, lane = tid & 31;
    int gID = lane >> 2, tig = lane & 3;
    int r0 = warp * 16 + gID;
    int r1 = r0 + 8;

    float acc[18][4];
    #pragma unroll
    for (int nt = 0; nt < 18; nt++)
        #pragma unroll
        for (int i = 0; i < 4; i++) acc[nt][i] = 0.f;

    #pragma unroll
    for (int ks = 0; ks < 4; ks++) {
        int k0 = ks * 8;
        uint32_t a0 = __float_as_uint(sq[r0 * QKST + k0 + tig]);
        uint32_t a1 = __float_as_uint(sq[r1 * QKST + k0 + tig]);
        uint32_t a2 = __float_as_uint(sq[r0 * QKST + k0 + tig + 4]);
        uint32_t a3 = __float_as_uint(sq[r1 * QKST + k0 + tig + 4]);
        #pragma unroll
        for (int nt = 0; nt < 18; nt++) {
            int n = nt * 8 + gID;
            uint32_t b0 = __float_as_uint(sk[n * QKST + k0 + tig]);
            uint32_t b1 = __float_as_uint(sk[n * QKST + k0 + tig + 4]);
            asm volatile(
                "mma.sync.aligned.m16n8k8.row.col.f32.tf32.tf32.f32 "
                "{%0,%1,%2,%3}, {%4,%5,%6,%7}, {%8,%9}, {%0,%1,%2,%3};"
                : "+f"(acc[nt][0]), "+f"(acc[nt][1]), "+f"(acc[nt][2]), "+f"(acc[nt][3])
                : "r"(a0), "r"(a1), "r"(a2), "r"(a3), "r"(b0), "r"(b1));
        }
    }

    int ri0 = sri[r0], ri1 = sri[r1];
    float mx0 = -1e30f, mx1 = -1e30f;
    #pragma unroll
    for (int nt = 0; nt < 18; nt++) {
        int j0 = nt * 8 + 2 * tig, j1 = j0 + 1;
        int c0 = scj[j0], c1 = scj[j1];
        acc[nt][0] += sb[ri0 + c0];
        acc[nt][1] += sb[ri0 + c1];
        acc[nt][2] += sb[ri1 + c0];
        acc[nt][3] += sb[ri1 + c1];
        mx0 = fmaxf(mx0, fmaxf(acc[nt][0], acc[nt][1]));
        mx1 = fmaxf(mx1, fmaxf(acc[nt][2], acc[nt][3]));
    }
    mx0 = fmaxf(mx0, __shfl_xor_sync(0xffffffffu, mx0, 1));
    mx0 = fmaxf(mx0, __shfl_xor_sync(0xffffffffu, mx0, 2));
    mx1 = fmaxf(mx1, __shfl_xor_sync(0xffffffffu, mx1, 1));
    mx1 = fmaxf(mx1, __shfl_xor_sync(0xffffffffu, mx1, 2));

    float s0 = 0.f, s1 = 0.f;
    #pragma unroll
    for (int nt = 0; nt < 18; nt++) {
        acc[nt][0] = __expf(acc[nt][0] - mx0);
        acc[nt][1] = __expf(acc[nt][1] - mx0);
        acc[nt][2] = __expf(acc[nt][2] - mx1);
        acc[nt][3] = __expf(acc[nt][3] - mx1);
        s0 += acc[nt][0] + acc[nt][1];
        s1 += acc[nt][2] + acc[nt][3];
    }
    s0 += __shfl_xor_sync(0xffffffffu, s0, 1);
    s0 += __shfl_xor_sync(0xffffffffu, s0, 2);
    s1 += __shfl_xor_sync(0xffffffffu, s1, 1);
    s1 += __shfl_xor_sync(0xffffffffu, s1, 2);
    float inv0 = 1.0f / s0, inv1 = 1.0f / s1;

    float* pw = sp + warp * 16 * PST;
    #pragma unroll
    for (int nt = 0; nt < 18; nt++) {
        int c = nt * 8 + 2 * tig;
        *(float2*)&pw[gID * PST + c]       = make_float2(tf32r(acc[nt][0] * inv0), tf32r(acc[nt][1] * inv0));
        *(float2*)&pw[(gID + 8) * PST + c] = make_float2(tf32r(acc[nt][2] * inv1), tf32r(acc[nt][3] * inv1));
    }
    __syncwarp();

    float oacc[4][4];
    #pragma unroll
    for (int nt = 0; nt < 4; nt++)
        #pragma unroll
        for (int i = 0; i < 4; i++) oacc[nt][i] = 0.f;

    #pragma unroll
    for (int ks = 0; ks < 18; ks++) {
        int k0 = ks * 8;
        uint32_t a0 = __float_as_uint(pw[gID * PST + k0 + tig]);
        uint32_t a1 = __float_as_uint(pw[(gID + 8) * PST + k0 + tig]);
        uint32_t a2 = __float_as_uint(pw[gID * PST + k0 + tig + 4]);
        uint32_t a3 = __float_as_uint(pw[(gID + 8) * PST + k0 + tig + 4]);
        #pragma unroll
        for (int nt = 0; nt < 4; nt++) {
            int n = nt * 8 + gID;
            uint32_t b0 = __float_as_uint(sv[(k0 + tig) * VST + n]);
            uint32_t b1 = __float_as_uint(sv[(k0 + tig + 4) * VST + n]);
            asm volatile(
                "mma.sync.aligned.m16n8k8.row.col.f32.tf32.tf32.f32 "
                "{%0,%1,%2,%3}, {%4,%5,%6,%7}, {%8,%9}, {%0,%1,%2,%3};"
                : "+f"(oacc[nt][0]), "+f"(oacc[nt][1]), "+f"(oacc[nt][2]), "+f"(oacc[nt][3])
                : "r"(a0), "r"(a1), "r"(a2), "r"(a3), "r"(b0), "r"(b1));
        }
    }

    #pragma unroll
    for (int nt = 0; nt < 4; nt++) {
        int c = h * HD + nt * 8 + 2 * tig;
        *(__nv_bfloat162*)&g_attn[(base + r0) * (size_t)DIM + c] = __floats2bfloat162_rn(oacc[nt][0], oacc[nt][1]);
        *(__nv_bfloat162*)&g_attn[(base + r1) * (size_t)DIM + c] = __floats2bfloat162_rn(oacc[nt][2], oacc[nt][3]);
    }
}

// ---------------- launch ----------------
extern "C" void kernel_launch(void* const* d_in, const int* in_sizes, int n_in,
                              void* d_out, int out_size) {
    const float* x          = (const float*)d_in[0];
    const float* norm1_g    = (const float*)d_in[1];
    const float* norm1_b    = (const float*)d_in[2];
    const float* qkv_w      = (const float*)d_in[3];
    const float* qkv_b      = (const float*)d_in[4];
    const float* bias_table = (const float*)d_in[5];
    const float* proj_w     = (const float*)d_in[6];
    const float* proj_b     = (const float*)d_in[7];
    const float* norm2_g    = (const float*)d_in[8];
    const float* norm2_b    = (const float*)d_in[9];
    const float* fc1_w      = (const float*)d_in[10];
    const float* fc1_b      = (const float*)d_in[11];
    const float* fc2_w      = (const float*)d_in[12];
    const float* fc2_b      = (const float*)d_in[13];
    float* out = (float*)d_out;

    bf16 *hw, *attn, *fc1, *ln2, *wqkv, *wproj, *wfc1, *wfc2;
    float *qkv, *x2, *projp;
    cudaGetSymbolAddress((void**)&hw,    g_hw);
    cudaGetSymbolAddress((void**)&qkv,   g_qkv);
    cudaGetSymbolAddress((void**)&attn,  g_attn);
    cudaGetSymbolAddress((void**)&fc1,   g_fc1);
    cudaGetSymbolAddress((void**)&ln2,   g_ln2);
    cudaGetSymbolAddress((void**)&x2,    g_x2);
    cudaGetSymbolAddress((void**)&projp, g_proj);
    cudaGetSymbolAddress((void**)&wqkv,  g_wqkv);
    cudaGetSymbolAddress((void**)&wproj, g_wproj);
    cudaGetSymbolAddress((void**)&wfc1,  g_wfc1);
    cudaGetSymbolAddress((void**)&wfc2,  g_wfc2);

    cudaFuncSetAttribute(attn_kernel, cudaFuncAttributeMaxDynamicSharedMemorySize, ATTN_SMEM_BYTES);

    // 0) weight conversion (tiny)
    f2bf_kernel<<<(3*DIM*DIM/4 + 255)/256, 256>>>(qkv_w,  wqkv,  3*DIM*DIM/4);
    f2bf_kernel<<<(DIM*DIM/4   + 255)/256, 256>>>(proj_w, wproj, DIM*DIM/4);
    f2bf_kernel<<<(HID*DIM/4   + 255)/256, 256>>>(fc1_w,  wfc1,  HID*DIM/4);
    f2bf_kernel<<<(DIM*HID/4   + 255)/256, 256>>>(fc2_w,  wfc2,  DIM*HID/4);

    // 1) LN1 + window partition (bf16)
    ln1_kernel<<<MTOK, 256>>>(x, norm1_g, norm1_b);

    // 2) QKV gemm -> float
    bgemm_kernel<false, false, false><<<dim3(768 / BN, MTOK / BM), 256>>>(
        hw, wqkv, qkv_b, nullptr, qkv, MTOK, 3 * DIM, DIM);

    // 3) windowed attention -> bf16
    attn_kernel<<<dim3(NW * (BATCH * NLON), HEADS), 288, ATTN_SMEM_BYTES>>>(bias_table);

    // 4) proj gemm -> float
    bgemm_kernel<false, false, false><<<dim3(DIM / BN, MTOK / BM), 256>>>(
        attn, wproj, proj_b, nullptr, projp, MTOK, DIM, DIM);

    // 5) window reverse + residual + LN2 (bf16)
    add_ln2_kernel<<<MTOK, 256>>>(x, norm2_g, norm2_b);

    // 6) fc1 gemm + gelu -> bf16
    bgemm_kernel<true, false, true><<<dim3(HID / BN, MTOK / BM), 256>>>(
        ln2, wfc1, fc1_b, nullptr, fc1, MTOK, HID, DIM);

    // 7) fc2 gemm + residual -> float out
    bgemm_kernel<false, true, false><<<dim3(DIM / BN, MTOK / BM), 256>>>(
        fc1, wfc2, fc2_b, x2, out, MTOK, DIM, HID);
}

// round 6
// speedup vs baseline: 4.4912x; 1.0675x over previous
#include <cuda_runtime.h>
#include <cuda_bf16.h>
#include <math.h>
#include <stdint.h>

// ---------------- problem constants ----------------
#define DIM   256
#define HEADS 8
#define HD    32
#define PL    8
#define LAT   60
#define LON   120
#define WPL   2
#define WLAT  6
#define WLON  12
#define NTOK  144
#define NPL   (PL/WPL)
#define NLAT  (LAT/WLAT)
#define NLON  (LON/WLON)
#define NW    (NPL*NLAT)     // 40
#define BATCH 2
#define LTOK  (PL*LAT*LON)   // 57600
#define MTOK  (BATCH*LTOK)   // 115200
#define HID   1024

typedef __nv_bfloat16 bf16;

// ---------------- scratch ----------------
__device__ bf16  g_hw  [(size_t)MTOK*DIM];
__device__ bf16  g_qkv [(size_t)MTOK*3*DIM];
__device__ bf16  g_attn[(size_t)MTOK*DIM];
__device__ float g_proj[(size_t)MTOK*DIM];
__device__ float g_x2  [(size_t)MTOK*DIM];
__device__ bf16  g_ln2 [(size_t)MTOK*DIM];
__device__ bf16  g_fc1 [(size_t)MTOK*HID];
__device__ bf16  g_wqkv [3*DIM*DIM];
__device__ bf16  g_wproj[DIM*DIM];
__device__ bf16  g_wfc1 [HID*DIM];
__device__ bf16  g_wfc2 [DIM*HID];

// ---------------- helpers ----------------
__device__ __forceinline__ int win_index(int t) {
    int b   = t / LTOK;
    int rem = t - b * LTOK;
    int pl  = rem / (LAT * LON);
    int r2  = rem - pl * (LAT * LON);
    int lat = r2 / LON;
    int lon = r2 - lat * LON;
    int np = pl / WPL,  ip = pl - np * WPL;
    int nl = lat / WLAT, il = lat - nl * WLAT;
    int no = lon / WLON, io = lon - no * WLON;
    int wb = b * NLON + no;
    int w  = np * NLAT + nl;
    int n  = (ip * WLAT + il) * WLON + io;
    return (wb * NW + w) * NTOK + n;
}

__device__ __forceinline__ uint32_t f2tf32(float f) {
    uint32_t u;
    asm("cvt.rna.tf32.f32 %0, %1;" : "=r"(u) : "f"(f));
    return u;
}
__device__ __forceinline__ float tf32r(float f) { return __uint_as_float(f2tf32(f)); }

__device__ __forceinline__ void warp_reduce2(float& a, float& b) {
    #pragma unroll
    for (int o = 16; o > 0; o >>= 1) {
        a += __shfl_xor_sync(0xffffffffu, a, o);
        b += __shfl_xor_sync(0xffffffffu, b, o);
    }
}

// ---------------- f32 -> bf16 weight conversion ----------------
__global__ void f2bf_kernel(const float* __restrict__ src, bf16* __restrict__ dst, int n4) {
    int i = blockIdx.x * blockDim.x + threadIdx.x;
    if (i < n4) {
        float4 v = *(const float4*)&src[i * 4];
        *(__nv_bfloat162*)&dst[i * 4]     = __floats2bfloat162_rn(v.x, v.y);
        *(__nv_bfloat162*)&dst[i * 4 + 2] = __floats2bfloat162_rn(v.z, v.w);
    }
}

// ---------------- LN1: warp per token, bf16 scatter ----------------
__global__ __launch_bounds__(256)
void ln1_kernel(const float* __restrict__ x,
                const float* __restrict__ g,
                const float* __restrict__ b) {
    int warp = threadIdx.x >> 5, lane = threadIdx.x & 31;
    int t = blockIdx.x * 8 + warp;
    const float4* xr = (const float4*)(x + (size_t)t * DIM);
    float4 u0 = xr[lane], u1 = xr[lane + 32];
    float s = u0.x + u0.y + u0.z + u0.w + u1.x + u1.y + u1.z + u1.w;
    float q = u0.x*u0.x + u0.y*u0.y + u0.z*u0.z + u0.w*u0.w
            + u1.x*u1.x + u1.y*u1.y + u1.z*u1.z + u1.w*u1.w;
    warp_reduce2(s, q);
    float mu  = s * (1.0f / DIM);
    float var = q * (1.0f / DIM) - mu * mu;
    float rs  = rsqrtf(fmaxf(var, 0.f) + 1e-5f);
    float4 g0 = ((const float4*)g)[lane], g1 = ((const float4*)g)[lane + 32];
    float4 b0 = ((const float4*)b)[lane], b1 = ((const float4*)b)[lane + 32];
    int wi = win_index(t);
    __nv_bfloat162* dst = (__nv_bfloat162*)(g_hw + (size_t)wi * DIM);
    dst[lane * 2]          = __floats2bfloat162_rn((u0.x - mu) * rs * g0.x + b0.x,
                                                   (u0.y - mu) * rs * g0.y + b0.y);
    dst[lane * 2 + 1]      = __floats2bfloat162_rn((u0.z - mu) * rs * g0.z + b0.z,
                                                   (u0.w - mu) * rs * g0.w + b0.w);
    dst[64 + lane * 2]     = __floats2bfloat162_rn((u1.x - mu) * rs * g1.x + b1.x,
                                                   (u1.y - mu) * rs * g1.y + b1.y);
    dst[64 + lane * 2 + 1] = __floats2bfloat162_rn((u1.z - mu) * rs * g1.z + b1.z,
                                                   (u1.w - mu) * rs * g1.w + b1.w);
}

// ---------------- residual add + LN2: warp per token ----------------
__global__ __launch_bounds__(256)
void add_ln2_kernel(const float* __restrict__ x,
                    const float* __restrict__ g,
                    const float* __restrict__ b) {
    int warp = threadIdx.x >> 5, lane = threadIdx.x & 31;
    int t = blockIdx.x * 8 + warp;
    int wi = win_index(t);
    const float4* xr = (const float4*)(x + (size_t)t * DIM);
    const float4* pr = (const float4*)(g_proj + (size_t)wi * DIM);
    float4 u0 = xr[lane], u1 = xr[lane + 32];
    float4 p0 = pr[lane], p1 = pr[lane + 32];
    u0.x += p0.x; u0.y += p0.y; u0.z += p0.z; u0.w += p0.w;
    u1.x += p1.x; u1.y += p1.y; u1.z += p1.z; u1.w += p1.w;
    float4* x2r = (float4*)(g_x2 + (size_t)t * DIM);
    x2r[lane] = u0; x2r[lane + 32] = u1;
    float s = u0.x + u0.y + u0.z + u0.w + u1.x + u1.y + u1.z + u1.w;
    float q = u0.x*u0.x + u0.y*u0.y + u0.z*u0.z + u0.w*u0.w
            + u1.x*u1.x + u1.y*u1.y + u1.z*u1.z + u1.w*u1.w;
    warp_reduce2(s, q);
    float mu  = s * (1.0f / DIM);
    float var = q * (1.0f / DIM) - mu * mu;
    float rs  = rsqrtf(fmaxf(var, 0.f) + 1e-5f);
    float4 g0 = ((const float4*)g)[lane], g1 = ((const float4*)g)[lane + 32];
    float4 b0 = ((const float4*)b)[lane], b1 = ((const float4*)b)[lane + 32];
    __nv_bfloat162* dst = (__nv_bfloat162*)(g_ln2 + (size_t)t * DIM);
    dst[lane * 2]          = __floats2bfloat162_rn((u0.x - mu) * rs * g0.x + b0.x,
                                                   (u0.y - mu) * rs * g0.y + b0.y);
    dst[lane * 2 + 1]      = __floats2bfloat162_rn((u0.z - mu) * rs * g0.z + b0.z,
                                                   (u0.w - mu) * rs * g0.w + b0.w);
    dst[64 + lane * 2]     = __floats2bfloat162_rn((u1.x - mu) * rs * g1.x + b1.x,
                                                   (u1.y - mu) * rs * g1.y + b1.y);
    dst[64 + lane * 2 + 1] = __floats2bfloat162_rn((u1.z - mu) * rs * g1.z + b1.z,
                                                   (u1.w - mu) * rs * g1.w + b1.w);
}

// ---------------- bf16 tensor-core GEMM with ldmatrix + 3-stage cp.async ----------------
#define BM 128
#define BN 128
#define BK 32
#define SAS 40                       // smem row stride in bf16 (80 B)
#define STG_BF (BM * SAS)
#define STG_BYTES (STG_BF * 2)

__device__ __forceinline__ void cp16(uint32_t smem_addr, const void* gmem_src) {
    asm volatile("cp.async.cg.shared.global [%0], [%1], 16;\n" :: "r"(smem_addr), "l"(gmem_src));
}
__device__ __forceinline__ void ldsm_x4(uint32_t& r0, uint32_t& r1, uint32_t& r2, uint32_t& r3,
                                        uint32_t addr) {
    asm volatile("ldmatrix.sync.aligned.m8n8.x4.shared.b16 {%0,%1,%2,%3}, [%4];"
                 : "=r"(r0), "=r"(r1), "=r"(r2), "=r"(r3) : "r"(addr));
}

template<bool GELU, bool RES, bool OBF>
__global__ __launch_bounds__(256)
void bgemm_kernel(const bf16* __restrict__ A,
                  const bf16* __restrict__ W,
                  const float* __restrict__ bias,
                  const float* __restrict__ res,
                  void* __restrict__ Cv,
                  int M, int N, int K) {
    __shared__ bf16 sA[3][STG_BF];
    __shared__ bf16 sB[3][STG_BF];

    int tid  = threadIdx.x;
    int bm   = blockIdx.y * BM;
    int bn   = blockIdx.x * BN;
    int warp = tid >> 5, lane = tid & 31;
    int wm = (warp & 3) * 32;
    int wn = (warp >> 2) * 64;
    int gID = lane >> 2;
    int tig = lane & 3;

    uint32_t aBase = (uint32_t)__cvta_generic_to_shared(&sA[0][0]);
    uint32_t bBase = (uint32_t)__cvta_generic_to_shared(&sB[0][0]);
    int seg = lane >> 3, ri = lane & 7;
    // A: matrices [rows0-7,k0-7],[rows8-15,k0-7],[rows0-7,k8-15],[rows8-15,k8-15]
    uint32_t aAddr = aBase + (uint32_t)(((wm + (seg & 1) * 8 + ri) * SAS + (seg >> 1) * 8) * 2);
    // B: matrices [n0-7,k0-7],[n0-7,k8-15],[n8-15,k0-7],[n8-15,k8-15]
    uint32_t bAddr = bBase + (uint32_t)(((wn + (seg >> 1) * 8 + ri) * SAS + (seg & 1) * 8) * 2);

    float acc[2][8][4];
    #pragma unroll
    for (int mt = 0; mt < 2; mt++)
        #pragma unroll
        for (int nt = 0; nt < 8; nt++)
            #pragma unroll
            for (int i = 0; i < 4; i++) acc[mt][nt][i] = 0.f;

    int niter = K / BK;
    int lrow = tid >> 2, lc = (tid & 3) * 8;

    auto load_stage = [&](int s, int k0) {
        #pragma unroll
        for (int r = 0; r < 2; r++) {
            int row = lrow + r * 64;
            uint32_t offA = aBase + (uint32_t)s * STG_BYTES + (uint32_t)((row * SAS + lc) * 2);
            uint32_t offB = bBase + (uint32_t)s * STG_BYTES + (uint32_t)((row * SAS + lc) * 2);
            cp16(offA, &A[(size_t)(bm + row) * K + k0 + lc]);
            cp16(offB, &W[(size_t)(bn + row) * K + k0 + lc]);
        }
        asm volatile("cp.async.commit_group;\n");
    };

    load_stage(0, 0);
    load_stage(1, BK);

    for (int it = 0; it < niter; it++) {
        int cur = it % 3;
        if (it == niter - 1) asm volatile("cp.async.wait_group 0;\n");
        else                 asm volatile("cp.async.wait_group 1;\n");
        __syncthreads();
        if (it + 2 < niter) load_stage((it + 2) % 3, (it + 2) * BK);

        uint32_t aS = aAddr + (uint32_t)cur * STG_BYTES;
        uint32_t bS = bAddr + (uint32_t)cur * STG_BYTES;

        #pragma unroll
        for (int ks = 0; ks < 2; ks++) {
            uint32_t ko = ks * 32;     // 16 bf16 = 32 B
            uint32_t af[2][4];
            ldsm_x4(af[0][0], af[0][1], af[0][2], af[0][3], aS + ko);
            ldsm_x4(af[1][0], af[1][1], af[1][2], af[1][3], aS + 16 * SAS * 2 + ko);
            uint32_t bfr[8][2];
            #pragma unroll
            for (int p = 0; p < 4; p++) {
                ldsm_x4(bfr[2*p][0], bfr[2*p][1], bfr[2*p+1][0], bfr[2*p+1][1],
                        bS + (uint32_t)(p * 16 * SAS * 2) + ko);
            }
            #pragma unroll
            for (int mt = 0; mt < 2; mt++)
                #pragma unroll
                for (int nt = 0; nt < 8; nt++) {
                    asm volatile(
                        "mma.sync.aligned.m16n8k16.row.col.f32.bf16.bf16.f32 "
                        "{%0,%1,%2,%3}, {%4,%5,%6,%7}, {%8,%9}, {%0,%1,%2,%3};"
                        : "+f"(acc[mt][nt][0]), "+f"(acc[mt][nt][1]),
                          "+f"(acc[mt][nt][2]), "+f"(acc[mt][nt][3])
                        : "r"(af[mt][0]), "r"(af[mt][1]), "r"(af[mt][2]), "r"(af[mt][3]),
                          "r"(bfr[nt][0]), "r"(bfr[nt][1]));
                }
        }
    }

    // epilogue
    float* Cf = (float*)Cv;
    bf16*  Cb = (bf16*)Cv;
    #pragma unroll
    for (int mt = 0; mt < 2; mt++) {
        int r0 = bm + wm + mt * 16 + gID;
        int r1 = r0 + 8;
        #pragma unroll
        for (int nt = 0; nt < 8; nt++) {
            int c = bn + wn + nt * 8 + tig * 2;
            float b0 = bias[c], b1 = bias[c + 1];
            float v00 = acc[mt][nt][0] + b0;
            float v01 = acc[mt][nt][1] + b1;
            float v10 = acc[mt][nt][2] + b0;
            float v11 = acc[mt][nt][3] + b1;
            if (GELU) {
                v00 = 0.5f * v00 * (1.0f + erff(v00 * 0.70710678118654752f));
                v01 = 0.5f * v01 * (1.0f + erff(v01 * 0.70710678118654752f));
                v10 = 0.5f * v10 * (1.0f + erff(v10 * 0.70710678118654752f));
                v11 = 0.5f * v11 * (1.0f + erff(v11 * 0.70710678118654752f));
            }
            size_t o0 = (size_t)r0 * N + c;
            size_t o1 = (size_t)r1 * N + c;
            if (RES) {
                float2 q0 = *(const float2*)&res[o0];
                float2 q1 = *(const float2*)&res[o1];
                v00 += q0.x; v01 += q0.y; v10 += q1.x; v11 += q1.y;
            }
            if (OBF) {
                *(__nv_bfloat162*)&Cb[o0] = __floats2bfloat162_rn(v00, v01);
                *(__nv_bfloat162*)&Cb[o1] = __floats2bfloat162_rn(v10, v11);
            } else {
                *(float2*)&Cf[o0] = make_float2(v00, v01);
                *(float2*)&Cf[o1] = make_float2(v10, v11);
            }
        }
    }
}

// ---------------- tensor-core windowed attention (tf32 math, bf16 in/out) ----------------
#define QKST 36
#define VST  40
#define PST  148
#define TBL  3312

#define SQ_OFF   0
#define SK_OFF   (NTOK*QKST)
#define SV_OFF   (SK_OFF + NTOK*QKST)
#define SP_OFF   (SV_OFF + NTOK*VST)
#define SB_OFF   (SP_OFF + 9*16*PST)
#define SI_OFF   (SB_OFF + TBL)
#define ATTN_SMEM_FLOATS (SI_OFF + 288)
#define ATTN_SMEM_BYTES  (ATTN_SMEM_FLOATS*4)

__global__ __launch_bounds__(288, 1)
void attn_kernel(const float* __restrict__ bias_table) {
    extern __shared__ float sm[];
    float* sq = sm + SQ_OFF;
    float* sk = sm + SK_OFF;
    float* sv = sm + SV_OFF;
    float* sp = sm + SP_OFF;
    float* sb = sm + SB_OFF;
    int*   sri = (int*)(sm + SI_OFF);
    int*   scj = sri + NTOK;

    int wg = blockIdx.x;
    int h  = blockIdx.y;
    int wt = wg % NW;
    int tid = threadIdx.x;
    size_t base = (size_t)wg * NTOK;
    const float scale = 0.17677669529663687f;

    if (tid < NTOK) {
        int i = tid;
        sri[i] = (i / 72) * 828 + ((i / 12) % 6) * 23 + (i % 12);
    } else {
        int j = tid - NTOK;
        scj[j] = (j / 72) * 1656 + ((j / 12) % 6) * 138 + (11 - (j % 12));
    }

    {
        int off = wt * HEADS + h;
        for (int idx = tid; idx < TBL; idx += 288)
            sb[idx] = __ldg(&bias_table[(size_t)idx * (NW * HEADS) + off]);
    }

    for (int idx = tid; idx < NTOK * 4; idx += 288) {
        int n = idx >> 2, e8 = (idx & 3) * 8;
        size_t toff = (base + n) * (size_t)(3 * DIM) + h * HD + e8;
        uint4 qr = *(const uint4*)&g_qkv[toff];
        uint4 kr = *(const uint4*)&g_qkv[toff + DIM];
        uint4 vr = *(const uint4*)&g_qkv[toff + 2 * DIM];
        const __nv_bfloat162* q2 = (const __nv_bfloat162*)&qr;
        const __nv_bfloat162* k2 = (const __nv_bfloat162*)&kr;
        const __nv_bfloat162* v2 = (const __nv_bfloat162*)&vr;
        #pragma unroll
        for (int p = 0; p < 4; p++) {
            float2 qf = __bfloat1622float2(q2[p]);
            float2 kf = __bfloat1622float2(k2[p]);
            float2 vf = __bfloat1622float2(v2[p]);
            sq[n * QKST + e8 + 2*p]     = tf32r(qf.x * scale);
            sq[n * QKST + e8 + 2*p + 1] = tf32r(qf.y * scale);
            sk[n * QKST + e8 + 2*p]     = kf.x;
            sk[n * QKST + e8 + 2*p + 1] = kf.y;
            sv[n * VST  + e8 + 2*p]     = vf.x;
            sv[n * VST  + e8 + 2*p + 1] = vf.y;
        }
    }
    __syncthreads();

    int warp = tid >> 5, lane = tid & 31;
    int gID = lane >> 2, tig = lane & 3;
    int r0 = warp * 16 + gID;
    int r1 = r0 + 8;

    float acc[18][4];
    #pragma unroll
    for (int nt = 0; nt < 18; nt++)
        #pragma unroll
        for (int i = 0; i < 4; i++) acc[nt][i] = 0.f;

    #pragma unroll
    for (int ks = 0; ks < 4; ks++) {
        int k0 = ks * 8;
        uint32_t a0 = __float_as_uint(sq[r0 * QKST + k0 + tig]);
        uint32_t a1 = __float_as_uint(sq[r1 * QKST + k0 + tig]);
        uint32_t a2 = __float_as_uint(sq[r0 * QKST + k0 + tig + 4]);
        uint32_t a3 = __float_as_uint(sq[r1 * QKST + k0 + tig + 4]);
        #pragma unroll
        for (int nt = 0; nt < 18; nt++) {
            int n = nt * 8 + gID;
            uint32_t b0 = __float_as_uint(sk[n * QKST + k0 + tig]);
            uint32_t b1 = __float_as_uint(sk[n * QKST + k0 + tig + 4]);
            asm volatile(
                "mma.sync.aligned.m16n8k8.row.col.f32.tf32.tf32.f32 "
                "{%0,%1,%2,%3}, {%4,%5,%6,%7}, {%8,%9}, {%0,%1,%2,%3};"
                : "+f"(acc[nt][0]), "+f"(acc[nt][1]), "+f"(acc[nt][2]), "+f"(acc[nt][3])
                : "r"(a0), "r"(a1), "r"(a2), "r"(a3), "r"(b0), "r"(b1));
        }
    }

    int ri0 = sri[r0], ri1 = sri[r1];
    float mx0 = -1e30f, mx1 = -1e30f;
    #pragma unroll
    for (int nt = 0; nt < 18; nt++) {
        int j0 = nt * 8 + 2 * tig, j1 = j0 + 1;
        int c0 = scj[j0], c1 = scj[j1];
        acc[nt][0] += sb[ri0 + c0];
        acc[nt][1] += sb[ri0 + c1];
        acc[nt][2] += sb[ri1 + c0];
        acc[nt][3] += sb[ri1 + c1];
        mx0 = fmaxf(mx0, fmaxf(acc[nt][0], acc[nt][1]));
        mx1 = fmaxf(mx1, fmaxf(acc[nt][2], acc[nt][3]));
    }
    mx0 = fmaxf(mx0, __shfl_xor_sync(0xffffffffu, mx0, 1));
    mx0 = fmaxf(mx0, __shfl_xor_sync(0xffffffffu, mx0, 2));
    mx1 = fmaxf(mx1, __shfl_xor_sync(0xffffffffu, mx1, 1));
    mx1 = fmaxf(mx1, __shfl_xor_sync(0xffffffffu, mx1, 2));

    float s0 = 0.f, s1 = 0.f;
    #pragma unroll
    for (int nt = 0; nt < 18; nt++) {
        acc[nt][0] = __expf(acc[nt][0] - mx0);
        acc[nt][1] = __expf(acc[nt][1] - mx0);
        acc[nt][2] = __expf(acc[nt][2] - mx1);
        acc[nt][3] = __expf(acc[nt][3] - mx1);
        s0 += acc[nt][0] + acc[nt][1];
        s1 += acc[nt][2] + acc[nt][3];
    }
    s0 += __shfl_xor_sync(0xffffffffu, s0, 1);
    s0 += __shfl_xor_sync(0xffffffffu, s0, 2);
    s1 += __shfl_xor_sync(0xffffffffu, s1, 1);
    s1 += __shfl_xor_sync(0xffffffffu, s1, 2);
    float inv0 = 1.0f / s0, inv1 = 1.0f / s1;

    float* pw = sp + warp * 16 * PST;
    #pragma unroll
    for (int nt = 0; nt < 18; nt++) {
        int c = nt * 8 + 2 * tig;
        *(float2*)&pw[gID * PST + c]       = make_float2(tf32r(acc[nt][0] * inv0), tf32r(acc[nt][1] * inv0));
        *(float2*)&pw[(gID + 8) * PST + c] = make_float2(tf32r(acc[nt][2] * inv1), tf32r(acc[nt][3] * inv1));
    }
    __syncwarp();

    float oacc[4][4];
    #pragma unroll
    for (int nt = 0; nt < 4; nt++)
        #pragma unroll
        for (int i = 0; i < 4; i++) oacc[nt][i] = 0.f;

    #pragma unroll
    for (int ks = 0; ks < 18; ks++) {
        int k0 = ks * 8;
        uint32_t a0 = __float_as_uint(pw[gID * PST + k0 + tig]);
        uint32_t a1 = __float_as_uint(pw[(gID + 8) * PST + k0 + tig]);
        uint32_t a2 = __float_as_uint(pw[gID * PST + k0 + tig + 4]);
        uint32_t a3 = __float_as_uint(pw[(gID + 8) * PST + k0 + tig + 4]);
        #pragma unroll
        for (int nt = 0; nt < 4; nt++) {
            int n = nt * 8 + gID;
            uint32_t b0 = __float_as_uint(sv[(k0 + tig) * VST + n]);
            uint32_t b1 = __float_as_uint(sv[(k0 + tig + 4) * VST + n]);
            asm volatile(
                "mma.sync.aligned.m16n8k8.row.col.f32.tf32.tf32.f32 "
                "{%0,%1,%2,%3}, {%4,%5,%6,%7}, {%8,%9}, {%0,%1,%2,%3};"
                : "+f"(oacc[nt][0]), "+f"(oacc[nt][1]), "+f"(oacc[nt][2]), "+f"(oacc[nt][3])
                : "r"(a0), "r"(a1), "r"(a2), "r"(a3), "r"(b0), "r"(b1));
        }
    }

    #pragma unroll
    for (int nt = 0; nt < 4; nt++) {
        int c = h * HD + nt * 8 + 2 * tig;
        *(__nv_bfloat162*)&g_attn[(base + r0) * (size_t)DIM + c] = __floats2bfloat162_rn(oacc[nt][0], oacc[nt][1]);
        *(__nv_bfloat162*)&g_attn[(base + r1) * (size_t)DIM + c] = __floats2bfloat162_rn(oacc[nt][2], oacc[nt][3]);
    }
}

// ---------------- launch ----------------
extern "C" void kernel_launch(void* const* d_in, const int* in_sizes, int n_in,
                              void* d_out, int out_size) {
    const float* x          = (const float*)d_in[0];
    const float* norm1_g    = (const float*)d_in[1];
    const float* norm1_b    = (const float*)d_in[2];
    const float* qkv_w      = (const float*)d_in[3];
    const float* qkv_b      = (const float*)d_in[4];
    const float* bias_table = (const float*)d_in[5];
    const float* proj_w     = (const float*)d_in[6];
    const float* proj_b     = (const float*)d_in[7];
    const float* norm2_g    = (const float*)d_in[8];
    const float* norm2_b    = (const float*)d_in[9];
    const float* fc1_w      = (const float*)d_in[10];
    const float* fc1_b      = (const float*)d_in[11];
    const float* fc2_w      = (const float*)d_in[12];
    const float* fc2_b      = (const float*)d_in[13];
    float* out = (float*)d_out;

    bf16 *hw, *qkv, *attn, *fc1, *ln2, *wqkv, *wproj, *wfc1, *wfc2;
    float *x2, *projp;
    cudaGetSymbolAddress((void**)&hw,    g_hw);
    cudaGetSymbolAddress((void**)&qkv,   g_qkv);
    cudaGetSymbolAddress((void**)&attn,  g_attn);
    cudaGetSymbolAddress((void**)&fc1,   g_fc1);
    cudaGetSymbolAddress((void**)&ln2,   g_ln2);
    cudaGetSymbolAddress((void**)&x2,    g_x2);
    cudaGetSymbolAddress((void**)&projp, g_proj);
    cudaGetSymbolAddress((void**)&wqkv,  g_wqkv);
    cudaGetSymbolAddress((void**)&wproj, g_wproj);
    cudaGetSymbolAddress((void**)&wfc1,  g_wfc1);
    cudaGetSymbolAddress((void**)&wfc2,  g_wfc2);

    cudaFuncSetAttribute(attn_kernel, cudaFuncAttributeMaxDynamicSharedMemorySize, ATTN_SMEM_BYTES);

    // 0) weight conversion (tiny)
    f2bf_kernel<<<(3*DIM*DIM/4 + 255)/256, 256>>>(qkv_w,  wqkv,  3*DIM*DIM/4);
    f2bf_kernel<<<(DIM*DIM/4   + 255)/256, 256>>>(proj_w, wproj, DIM*DIM/4);
    f2bf_kernel<<<(HID*DIM/4   + 255)/256, 256>>>(fc1_w,  wfc1,  HID*DIM/4);
    f2bf_kernel<<<(DIM*HID/4   + 255)/256, 256>>>(fc2_w,  wfc2,  DIM*HID/4);

    // 1) LN1 + window partition (bf16)
    ln1_kernel<<<MTOK / 8, 256>>>(x, norm1_g, norm1_b);

    // 2) QKV gemm -> bf16
    bgemm_kernel<false, false, true><<<dim3(768 / BN, MTOK / BM), 256>>>(
        hw, wqkv, qkv_b, nullptr, qkv, MTOK, 3 * DIM, DIM);

    // 3) windowed attention -> bf16
    attn_kernel<<<dim3(NW * (BATCH * NLON), HEADS), 288, ATTN_SMEM_BYTES>>>(bias_table);

    // 4) proj gemm -> float
    bgemm_kernel<false, false, false><<<dim3(DIM / BN, MTOK / BM), 256>>>(
        attn, wproj, proj_b, nullptr, projp, MTOK, DIM, DIM);

    // 5) window reverse + residual + LN2 (bf16)
    add_ln2_kernel<<<MTOK / 8, 256>>>(x, norm2_g, norm2_b);

    // 6) fc1 gemm + gelu -> bf16
    bgemm_kernel<true, false, true><<<dim3(HID / BN, MTOK / BM), 256>>>(
        ln2, wfc1, fc1_b, nullptr, fc1, MTOK, HID, DIM);

    // 7) fc2 gemm + residual -> float out
    bgemm_kernel<false, true, false><<<dim3(DIM / BN, MTOK / BM), 256>>>(
        fc1, wfc2, fc2_b, x2, out, MTOK, DIM, HID);
}